// round 1
// baseline (speedup 1.0000x reference)
#include <cuda_runtime.h>
#include <cstdint>

#define T_SEQ 2048
#define BATCH 2
#define EMBED 512
#define NHEADS 8
#define HD 64
#define FFN_DIM 2048
#define NROWS (T_SEQ * BATCH)      // 4096
#define BH (BATCH * NHEADS)        // 16
#define QKV_LD (3 * EMBED)         // 1536
#define ROWSTRIDE (BATCH * QKV_LD) // 3072

// ---------------- device scratch (static globals; no allocation) ----------------
__device__ float g_x[NROWS * EMBED];                       // 8 MB  current activations
__device__ float g_qkv[NROWS * QKV_LD];                    // 24 MB q|k|v
__device__ float g_W[(size_t)BH * T_SEQ * T_SEQ];          // 256 MB raw masked scores
__device__ float g_attn[NROWS * EMBED];                    // 8 MB  attn "a" matrix / ffn out
__device__ float g_tmp[NROWS * FFN_DIM];                   // 32 MB proj out / ffn hidden
__device__ float g_vsum[BH * HD];
__device__ unsigned g_minmax[2];                           // [0]=min enc, [1]=max enc

// orderable-uint encoding of float (monotonic): enables atomicMin/Max on floats
__device__ __forceinline__ unsigned fenc(float f) {
    unsigned u = __float_as_uint(f);
    return (u & 0x80000000u) ? ~u : (u | 0x80000000u);
}
__device__ __forceinline__ float fdec(unsigned e) {
    return __uint_as_float((e & 0x80000000u) ? (e ^ 0x80000000u) : ~e);
}

__global__ void minmax_init_kernel() {
    g_minmax[0] = 0xFFFFFFFFu;  // +inf encoded-min start
    g_minmax[1] = 0u;           // -inf encoded-max start
}

// ---------------- positional embedding: x += sinusoidal(pe) ----------------
__global__ void posembed_kernel(const float* __restrict__ x,
                                const int* __restrict__ tokens,
                                float* __restrict__ out) {
    int idx = blockIdx.x * blockDim.x + threadIdx.x;  // NROWS*EMBED
    int c = idx & (EMBED - 1);
    int row = idx >> 9;               // EMBED = 512
    int t = row >> 1;                 // BATCH = 2
    int b = row & 1;
    int tok = tokens[b * T_SEQ + t];
    float pe = 0.f;
    if (tok != 0) {
        float p = (float)(t + 1);
        int i = (c < 256) ? c : c - 256;
        float ang = p * expf((float)i * (-9.210340371976184f / 255.0f));
        pe = (c < 256) ? sinf(ang) : cosf(ang);
    }
    out[idx] = x[idx] + pe;
}

// ---------------- generic SGEMM: C[m,n] = sum_k A[m,k]*B[n,k] + bias[n] (opt relu)
// A row-stride = K, B is [N,K] row-major (weights). Dual-A: n >= nsplit uses Akv.
__global__ __launch_bounds__(256, 2)
void sgemm_kernel(const float* __restrict__ Aq, const float* __restrict__ Akv, int nsplit,
                  const float* __restrict__ Bw, const float* __restrict__ bias,
                  float* __restrict__ Cmat, int M, int N, int K, int relu) {
    __shared__ float As[8][128];
    __shared__ float Bs[8][128];
    const int bm = blockIdx.y * 128;
    const int bn = blockIdx.x * 128;
    const float* A = (bn < nsplit) ? Aq : Akv;
    const int tid = threadIdx.x;
    const int lr = tid >> 1;
    const int lc = (tid & 1) * 4;
    const float* Aptr = A + (size_t)(bm + lr) * K + lc;
    const float* Bptr = Bw + (size_t)(bn + lr) * K + lc;
    const int tx = tid & 15, ty = tid >> 4;

    float acc[8][8];
#pragma unroll
    for (int i = 0; i < 8; i++)
#pragma unroll
        for (int j = 0; j < 8; j++) acc[i][j] = 0.f;

    for (int k0 = 0; k0 < K; k0 += 8) {
        float4 av = *(const float4*)(Aptr + k0);
        float4 bv = *(const float4*)(Bptr + k0);
        As[lc + 0][lr] = av.x; As[lc + 1][lr] = av.y; As[lc + 2][lr] = av.z; As[lc + 3][lr] = av.w;
        Bs[lc + 0][lr] = bv.x; Bs[lc + 1][lr] = bv.y; Bs[lc + 2][lr] = bv.z; Bs[lc + 3][lr] = bv.w;
        __syncthreads();
#pragma unroll
        for (int k = 0; k < 8; k++) {
            float a[8], bb[8];
            *(float4*)(a)     = *(const float4*)(&As[k][ty * 8]);
            *(float4*)(a + 4) = *(const float4*)(&As[k][ty * 8 + 4]);
            *(float4*)(bb)     = *(const float4*)(&Bs[k][tx * 8]);
            *(float4*)(bb + 4) = *(const float4*)(&Bs[k][tx * 8 + 4]);
#pragma unroll
            for (int i = 0; i < 8; i++)
#pragma unroll
                for (int j = 0; j < 8; j++)
                    acc[i][j] = fmaf(a[i], bb[j], acc[i][j]);
        }
        __syncthreads();
    }
#pragma unroll
    for (int i = 0; i < 8; i++) {
        const int m = bm + ty * 8 + i;
#pragma unroll
        for (int j = 0; j < 8; j += 4) {
            const int n = bn + tx * 8 + j;
            float4 v;
            v.x = acc[i][j + 0] + bias[n + 0];
            v.y = acc[i][j + 1] + bias[n + 1];
            v.z = acc[i][j + 2] + bias[n + 2];
            v.w = acc[i][j + 3] + bias[n + 3];
            if (relu) {
                v.x = fmaxf(v.x, 0.f); v.y = fmaxf(v.y, 0.f);
                v.z = fmaxf(v.z, 0.f); v.w = fmaxf(v.w, 0.f);
            }
            *(float4*)(Cmat + (size_t)m * N + n) = v;
        }
    }
}

// ---------------- scores: W[bh,t,s] = (q.k)*scale * mask; fused global min/max ----
__global__ __launch_bounds__(256, 2)
void scores_kernel(int selfmask) {
    __shared__ float As[8][128];
    __shared__ float Bs[8][128];
    const int bh = blockIdx.z;
    const int b = bh >> 3, h = bh & 7;
    const int bt = blockIdx.y * 128;
    const int bs = blockIdx.x * 128;
    float* Wout = g_W + (size_t)bh * T_SEQ * T_SEQ;
    const int tid = threadIdx.x;

    if (selfmask && bs > bt + 127) {  // fully masked tile: zeros only
        const int r = tid >> 1;
        const int c0 = (tid & 1) * 64;
        float4 z = make_float4(0.f, 0.f, 0.f, 0.f);
        float* p = Wout + (size_t)(bt + r) * T_SEQ + bs + c0;
#pragma unroll
        for (int j = 0; j < 64; j += 4) *(float4*)(p + j) = z;
        if (tid == 0) {
            atomicMin(&g_minmax[0], fenc(0.f));
            atomicMax(&g_minmax[1], fenc(0.f));
        }
        return;
    }

    const float* qb = g_qkv + b * QKV_LD + h * HD;
    const float* kb = g_qkv + b * QKV_LD + EMBED + h * HD;
    const int lr = tid >> 1, lc = (tid & 1) * 4;
    const int tx = tid & 15, ty = tid >> 4;
    float acc[8][8];
#pragma unroll
    for (int i = 0; i < 8; i++)
#pragma unroll
        for (int j = 0; j < 8; j++) acc[i][j] = 0.f;

    for (int k0 = 0; k0 < HD; k0 += 8) {
        float4 av = *(const float4*)(qb + (size_t)(bt + lr) * ROWSTRIDE + k0 + lc);
        float4 bv = *(const float4*)(kb + (size_t)(bs + lr) * ROWSTRIDE + k0 + lc);
        As[lc + 0][lr] = av.x; As[lc + 1][lr] = av.y; As[lc + 2][lr] = av.z; As[lc + 3][lr] = av.w;
        Bs[lc + 0][lr] = bv.x; Bs[lc + 1][lr] = bv.y; Bs[lc + 2][lr] = bv.z; Bs[lc + 3][lr] = bv.w;
        __syncthreads();
#pragma unroll
        for (int k = 0; k < 8; k++) {
            float a[8], bb[8];
            *(float4*)(a)     = *(const float4*)(&As[k][ty * 8]);
            *(float4*)(a + 4) = *(const float4*)(&As[k][ty * 8 + 4]);
            *(float4*)(bb)     = *(const float4*)(&Bs[k][tx * 8]);
            *(float4*)(bb + 4) = *(const float4*)(&Bs[k][tx * 8 + 4]);
#pragma unroll
            for (int i = 0; i < 8; i++)
#pragma unroll
                for (int j = 0; j < 8; j++)
                    acc[i][j] = fmaf(a[i], bb[j], acc[i][j]);
        }
        __syncthreads();
    }

    float lmin = 3.4e38f, lmax = -3.4e38f;
#pragma unroll
    for (int i = 0; i < 8; i++) {
        const int t = bt + ty * 8 + i;
#pragma unroll
        for (int j = 0; j < 8; j += 4) {
            const int s = bs + tx * 8 + j;
            float4 v;
            v.x = acc[i][j + 0] * 0.125f;
            v.y = acc[i][j + 1] * 0.125f;
            v.z = acc[i][j + 2] * 0.125f;
            v.w = acc[i][j + 3] * 0.125f;
            if (selfmask) {
                if (s + 0 > t) v.x = 0.f;
                if (s + 1 > t) v.y = 0.f;
                if (s + 2 > t) v.z = 0.f;
                if (s + 3 > t) v.w = 0.f;
            }
            lmin = fminf(lmin, fminf(fminf(v.x, v.y), fminf(v.z, v.w)));
            lmax = fmaxf(lmax, fmaxf(fmaxf(v.x, v.y), fmaxf(v.z, v.w)));
            *(float4*)(Wout + (size_t)t * T_SEQ + s) = v;
        }
    }

    float* red = &As[0][0];
    float* red2 = &Bs[0][0];
    red[tid] = lmin;
    red2[tid] = lmax;
    __syncthreads();
    for (int sft = 128; sft > 0; sft >>= 1) {
        if (tid < sft) {
            red[tid] = fminf(red[tid], red[tid + sft]);
            red2[tid] = fmaxf(red2[tid], red2[tid + sft]);
        }
        __syncthreads();
    }
    if (tid == 0) {
        atomicMin(&g_minmax[0], fenc(red[0]));
        atomicMax(&g_minmax[1], fenc(red2[0]));
    }
}

// ---------------- colsum of V per (bh, d) ----------------
__global__ void vsum_kernel() {
    const int bh = blockIdx.x;
    const int b = bh >> 3, h = bh & 7;
    const float* vb = g_qkv + b * QKV_LD + 2 * EMBED + h * HD;
    const int d = threadIdx.x & 63;
    const int part = threadIdx.x >> 6;
    float s = 0.f;
    for (int i = part * 512; i < part * 512 + 512; i++)
        s += vb[(size_t)i * ROWSTRIDE + d];
    __shared__ float sm[256];
    sm[threadIdx.x] = s;
    __syncthreads();
    if (threadIdx.x < 64)
        g_vsum[bh * 64 + d] = sm[d] + sm[64 + d] + sm[128 + d] + sm[192 + d];
}

// ---------------- AV: a = (W@V - mn*Vsum) / (mx-mn), written back as [T*B, C] ----
__global__ __launch_bounds__(256, 2)
void av_kernel(int selfmask) {
    __shared__ float As[8][128];
    __shared__ float Bs[8][64];
    const int bh = blockIdx.z;
    const int b = bh >> 3, h = bh & 7;
    const int bm = blockIdx.y * 128;
    const float* Wm = g_W + (size_t)bh * T_SEQ * T_SEQ;
    const float* vb = g_qkv + b * QKV_LD + 2 * EMBED + h * HD;
    const int tid = threadIdx.x;
    const int lr = tid >> 1, lc = (tid & 1) * 4;
    const int tx = tid & 15, ty = tid >> 4;
    float acc[8][4];
#pragma unroll
    for (int i = 0; i < 8; i++)
#pragma unroll
        for (int j = 0; j < 4; j++) acc[i][j] = 0.f;

    const int kmax = selfmask ? (bm + 128) : T_SEQ;  // W is exactly 0 beyond diag
    for (int k0 = 0; k0 < kmax; k0 += 8) {
        float4 av = *(const float4*)(Wm + (size_t)(bm + lr) * T_SEQ + k0 + lc);
        As[lc + 0][lr] = av.x; As[lc + 1][lr] = av.y; As[lc + 2][lr] = av.z; As[lc + 3][lr] = av.w;
        if (tid < 128) {
            const int rb = tid >> 4, cb = (tid & 15) * 4;
            *(float4*)(&Bs[rb][cb]) = *(const float4*)(vb + (size_t)(k0 + rb) * ROWSTRIDE + cb);
        }
        __syncthreads();
#pragma unroll
        for (int k = 0; k < 8; k++) {
            float a[8];
            *(float4*)(a)     = *(const float4*)(&As[k][ty * 8]);
            *(float4*)(a + 4) = *(const float4*)(&As[k][ty * 8 + 4]);
            float4 bb = *(const float4*)(&Bs[k][tx * 4]);
#pragma unroll
            for (int i = 0; i < 8; i++) {
                acc[i][0] = fmaf(a[i], bb.x, acc[i][0]);
                acc[i][1] = fmaf(a[i], bb.y, acc[i][1]);
                acc[i][2] = fmaf(a[i], bb.z, acc[i][2]);
                acc[i][3] = fmaf(a[i], bb.w, acc[i][3]);
            }
        }
        __syncthreads();
    }

    const float mn = fdec(g_minmax[0]);
    const float mx = fdec(g_minmax[1]);
    const float inv = 1.f / (mx - mn);
    const int n0 = tx * 4;
    float4 vs = *(const float4*)(g_vsum + bh * 64 + n0);
#pragma unroll
    for (int i = 0; i < 8; i++) {
        const int t = bm + ty * 8 + i;
        float4 o;
        o.x = (acc[i][0] - mn * vs.x) * inv;
        o.y = (acc[i][1] - mn * vs.y) * inv;
        o.z = (acc[i][2] - mn * vs.z) * inv;
        o.w = (acc[i][3] - mn * vs.w) * inv;
        *(float4*)(g_attn + (size_t)(t * BATCH + b) * EMBED + h * HD + n0) = o;
    }
}

// ---------------- fused residual + LayerNorm ----------------
__global__ void ln_kernel(const float* __restrict__ res, const float* __restrict__ y,
                          const float* __restrict__ gam, const float* __restrict__ bet,
                          float* __restrict__ out) {
    const int row = blockIdx.x;
    const int tid = threadIdx.x;  // 128 threads, 4 elems each
    const size_t base = (size_t)row * EMBED;
    float4 r4 = *(const float4*)(res + base + tid * 4);
    float4 y4 = *(const float4*)(y + base + tid * 4);
    float v0 = r4.x + y4.x, v1 = r4.y + y4.y, v2 = r4.z + y4.z, v3 = r4.w + y4.w;
    float s = v0 + v1 + v2 + v3;
    float q = v0 * v0 + v1 * v1 + v2 * v2 + v3 * v3;
#pragma unroll
    for (int off = 16; off > 0; off >>= 1) {
        s += __shfl_down_sync(0xffffffffu, s, off);
        q += __shfl_down_sync(0xffffffffu, q, off);
    }
    __shared__ float sm[8];
    __shared__ float stats[2];
    const int wid = tid >> 5, lane = tid & 31;
    if (lane == 0) { sm[wid] = s; sm[4 + wid] = q; }
    __syncthreads();
    if (tid == 0) {
        float S = sm[0] + sm[1] + sm[2] + sm[3];
        float Q = sm[4] + sm[5] + sm[6] + sm[7];
        float mu = S * (1.f / 512.f);
        float var = Q * (1.f / 512.f) - mu * mu;
        stats[0] = mu;
        stats[1] = rsqrtf(fmaxf(var, 0.f) + 1e-20f);
    }
    __syncthreads();
    const float mu = stats[0], rs = stats[1];
    const int c = tid * 4;
    float4 g4 = *(const float4*)(gam + c);
    float4 b4 = *(const float4*)(bet + c);
    float4 o;
    o.x = (v0 - mu) * rs * g4.x + b4.x;
    o.y = (v1 - mu) * rs * g4.y + b4.y;
    o.z = (v2 - mu) * rs * g4.z + b4.z;
    o.w = (v3 - mu) * rs * g4.w + b4.w;
    *(float4*)(out + base + c) = o;
}

// ---------------- host orchestration ----------------
extern "C" void kernel_launch(void* const* d_in, const int* in_sizes, int n_in,
                              void* d_out, int out_size) {
    const float* x         = (const float*)d_in[0];
    const float* enc_out   = (const float*)d_in[1];
    const int*   tokens    = (const int*)d_in[2];
    const float* self_Wqkv = (const float*)d_in[3];
    const float* self_bqkv = (const float*)d_in[4];
    const float* self_Wo   = (const float*)d_in[5];
    const float* self_bo   = (const float*)d_in[6];
    const float* cross_Wqkv= (const float*)d_in[7];
    const float* cross_bqkv= (const float*)d_in[8];
    const float* cross_Wo  = (const float*)d_in[9];
    const float* cross_bo  = (const float*)d_in[10];
    const float* fc1_w     = (const float*)d_in[11];
    const float* fc1_b     = (const float*)d_in[12];
    const float* fc2_w     = (const float*)d_in[13];
    const float* fc2_b     = (const float*)d_in[14];
    const float* ln1_g     = (const float*)d_in[15];
    const float* ln1_b     = (const float*)d_in[16];
    const float* ln2_g     = (const float*)d_in[17];
    const float* ln2_b     = (const float*)d_in[18];
    const float* ln3_g     = (const float*)d_in[19];
    const float* ln3_b     = (const float*)d_in[20];

    float *px, *pqkv, *pattn, *ptmp;
    cudaGetSymbolAddress((void**)&px, g_x);
    cudaGetSymbolAddress((void**)&pqkv, g_qkv);
    cudaGetSymbolAddress((void**)&pattn, g_attn);
    cudaGetSymbolAddress((void**)&ptmp, g_tmp);

    const int BIG = 1 << 30;

    posembed_kernel<<<(NROWS * EMBED) / 256, 256>>>(x, tokens, px);

    for (int l = 0; l < 4; l++) {
        // ---- self attention ----
        minmax_init_kernel<<<1, 1>>>();
        sgemm_kernel<<<dim3(12, 32), 256>>>(px, px, BIG,
            self_Wqkv + (size_t)l * QKV_LD * EMBED, self_bqkv + l * QKV_LD,
            pqkv, NROWS, QKV_LD, EMBED, 0);
        scores_kernel<<<dim3(16, 16, 16), 256>>>(1);
        vsum_kernel<<<16, 256>>>();
        av_kernel<<<dim3(1, 16, 16), 256>>>(1);
        sgemm_kernel<<<dim3(4, 32), 256>>>(pattn, pattn, BIG,
            self_Wo + (size_t)l * EMBED * EMBED, self_bo + l * EMBED,
            ptmp, NROWS, EMBED, EMBED, 0);
        ln_kernel<<<NROWS, 128>>>(px, ptmp, ln1_g + l * EMBED, ln1_b + l * EMBED, px);

        // ---- cross attention (kv from enc_out) ----
        minmax_init_kernel<<<1, 1>>>();
        sgemm_kernel<<<dim3(12, 32), 256>>>(px, enc_out, EMBED,
            cross_Wqkv + (size_t)l * QKV_LD * EMBED, cross_bqkv + l * QKV_LD,
            pqkv, NROWS, QKV_LD, EMBED, 0);
        scores_kernel<<<dim3(16, 16, 16), 256>>>(0);
        vsum_kernel<<<16, 256>>>();
        av_kernel<<<dim3(1, 16, 16), 256>>>(0);
        sgemm_kernel<<<dim3(4, 32), 256>>>(pattn, pattn, BIG,
            cross_Wo + (size_t)l * EMBED * EMBED, cross_bo + l * EMBED,
            ptmp, NROWS, EMBED, EMBED, 0);
        ln_kernel<<<NROWS, 128>>>(px, ptmp, ln2_g + l * EMBED, ln2_b + l * EMBED, px);

        // ---- FFN ----
        sgemm_kernel<<<dim3(16, 32), 256>>>(px, px, BIG,
            fc1_w + (size_t)l * FFN_DIM * EMBED, fc1_b + l * FFN_DIM,
            ptmp, NROWS, FFN_DIM, EMBED, 1);
        sgemm_kernel<<<dim3(4, 32), 256>>>(ptmp, ptmp, BIG,
            fc2_w + (size_t)l * EMBED * FFN_DIM, fc2_b + l * EMBED,
            pattn, NROWS, EMBED, FFN_DIM, 0);
        float* lnout = (l == 3) ? (float*)d_out : px;
        ln_kernel<<<NROWS, 128>>>(px, pattn, ln3_g + l * EMBED, ln3_b + l * EMBED, lnout);
    }
}

// round 3
// speedup vs baseline: 1.3507x; 1.3507x over previous
#include <cuda_runtime.h>
#include <cuda_bf16.h>
#include <cstdint>

#define T_SEQ 2048
#define BATCH 2
#define EMBED 512
#define NHEADS 8
#define HD 64
#define FFN_DIM 2048
#define NROWS (T_SEQ * BATCH)      // 4096
#define BH (BATCH * NHEADS)        // 16
#define QKV_LD (3 * EMBED)         // 1536
#define ROWSTRIDE (BATCH * QKV_LD) // 3072
#define TT ((size_t)T_SEQ * T_SEQ)
#define S32 40                     // smem row stride (elems) for 32-col bf16 tiles
#define S64 72                     // smem row stride (elems) for 64-col bf16 tiles

// ---------------- device scratch ----------------
__device__ __align__(16) float g_x[NROWS * EMBED];
__device__ __align__(16) float g_qkv[NROWS * QKV_LD];
__device__ __align__(16) float g_W[BH * TT];          // aliased as 2 bf16 planes hi|lo
__device__ __align__(16) float g_attn[NROWS * EMBED];
__device__ __align__(16) float g_tmp[NROWS * FFN_DIM]; // ffn hidden / Vt planes / proj out
__device__ float g_vsum[BH * HD];
__device__ unsigned g_minmax[2];

// orderable-uint encoding of float
__device__ __forceinline__ unsigned fenc(float f) {
    unsigned u = __float_as_uint(f);
    return (u & 0x80000000u) ? ~u : (u | 0x80000000u);
}
__device__ __forceinline__ float fdec(unsigned e) {
    return __uint_as_float((e & 0x80000000u) ? (e ^ 0x80000000u) : ~e);
}

__device__ __forceinline__ uint32_t smem_u32(const void* p) {
    uint32_t a;
    asm("{ .reg .u64 t; cvta.to.shared.u64 t, %1; cvt.u32.u64 %0, t; }" : "=r"(a) : "l"(p));
    return a;
}

__device__ __forceinline__ void ldmx4(uint32_t* r, uint32_t addr) {
    asm volatile("ldmatrix.sync.aligned.m8n8.x4.shared.b16 {%0,%1,%2,%3}, [%4];"
        : "=r"(r[0]), "=r"(r[1]), "=r"(r[2]), "=r"(r[3]) : "r"(addr));
}

__device__ __forceinline__ void mma16816(float* c, const uint32_t* a, const uint32_t* b) {
    asm volatile("mma.sync.aligned.m16n8k16.row.col.f32.bf16.bf16.f32 "
        "{%0,%1,%2,%3}, {%4,%5,%6,%7}, {%8,%9}, {%0,%1,%2,%3};"
        : "+f"(c[0]), "+f"(c[1]), "+f"(c[2]), "+f"(c[3])
        : "r"(a[0]), "r"(a[1]), "r"(a[2]), "r"(a[3]), "r"(b[0]), "r"(b[1]));
}

// fp32 quad -> bf16 hi/lo pairs
__device__ __forceinline__ void cvt4(float4 v, uint2& uh, uint2& ul) {
    __nv_bfloat162 h01 = __floats2bfloat162_rn(v.x, v.y);
    __nv_bfloat162 h23 = __floats2bfloat162_rn(v.z, v.w);
    float2 f01 = __bfloat1622float2(h01);
    float2 f23 = __bfloat1622float2(h23);
    __nv_bfloat162 l01 = __floats2bfloat162_rn(v.x - f01.x, v.y - f01.y);
    __nv_bfloat162 l23 = __floats2bfloat162_rn(v.z - f23.x, v.w - f23.y);
    uh.x = *(uint32_t*)&h01; uh.y = *(uint32_t*)&h23;
    ul.x = *(uint32_t*)&l01; ul.y = *(uint32_t*)&l23;
}

// ---------------- misc small kernels ----------------
__global__ void minmax_init_kernel(int selfmask) {
    if (selfmask) { g_minmax[0] = fenc(0.f); g_minmax[1] = fenc(0.f); }
    else          { g_minmax[0] = 0xFFFFFFFFu; g_minmax[1] = 0u; }
}

__global__ void posembed_kernel(const float* __restrict__ x,
                                const int* __restrict__ tokens,
                                float* __restrict__ out) {
    int idx = blockIdx.x * blockDim.x + threadIdx.x;
    int c = idx & (EMBED - 1);
    int row = idx >> 9;
    int t = row >> 1;
    int b = row & 1;
    int tok = tokens[b * T_SEQ + t];
    float pe = 0.f;
    if (tok != 0) {
        float p = (float)(t + 1);
        int i = (c < 256) ? c : c - 256;
        float ang = p * expf((float)i * (-9.210340371976184f / 255.0f));
        pe = (c < 256) ? sinf(ang) : cosf(ang);
    }
    out[idx] = x[idx] + pe;
}

__global__ void vsum_kernel() {
    const int bh = blockIdx.x;
    const int b = bh >> 3, h = bh & 7;
    const float* vb = g_qkv + b * QKV_LD + 2 * EMBED + h * HD;
    const int d = threadIdx.x & 63;
    const int part = threadIdx.x >> 6;
    float s = 0.f;
    for (int i = part * 512; i < part * 512 + 512; i++)
        s += vb[(size_t)i * ROWSTRIDE + d];
    __shared__ float sm[256];
    sm[threadIdx.x] = s;
    __syncthreads();
    if (threadIdx.x < 64)
        g_vsum[bh * 64 + d] = sm[d] + sm[64 + d] + sm[128 + d] + sm[192 + d];
}

__global__ void ln_kernel(const float* __restrict__ res, const float* __restrict__ y,
                          const float* __restrict__ gam, const float* __restrict__ bet,
                          float* __restrict__ out) {
    const int row = blockIdx.x;
    const int tid = threadIdx.x;
    const size_t base = (size_t)row * EMBED;
    float4 r4 = *(const float4*)(res + base + tid * 4);
    float4 y4 = *(const float4*)(y + base + tid * 4);
    float v0 = r4.x + y4.x, v1 = r4.y + y4.y, v2 = r4.z + y4.z, v3 = r4.w + y4.w;
    float s = v0 + v1 + v2 + v3;
    float q = v0 * v0 + v1 * v1 + v2 * v2 + v3 * v3;
#pragma unroll
    for (int off = 16; off > 0; off >>= 1) {
        s += __shfl_down_sync(0xffffffffu, s, off);
        q += __shfl_down_sync(0xffffffffu, q, off);
    }
    __shared__ float sm[8];
    __shared__ float stats[2];
    const int wid = tid >> 5, lane = tid & 31;
    if (lane == 0) { sm[wid] = s; sm[4 + wid] = q; }
    __syncthreads();
    if (tid == 0) {
        float S = sm[0] + sm[1] + sm[2] + sm[3];
        float Q = sm[4] + sm[5] + sm[6] + sm[7];
        float mu = S * (1.f / 512.f);
        float var = Q * (1.f / 512.f) - mu * mu;
        stats[0] = mu;
        stats[1] = rsqrtf(fmaxf(var, 0.f) + 1e-20f);
    }
    __syncthreads();
    const float mu = stats[0], rs = stats[1];
    const int c = tid * 4;
    float4 g4 = *(const float4*)(gam + c);
    float4 b4 = *(const float4*)(bet + c);
    float4 o;
    o.x = (v0 - mu) * rs * g4.x + b4.x;
    o.y = (v1 - mu) * rs * g4.y + b4.y;
    o.z = (v2 - mu) * rs * g4.z + b4.z;
    o.w = (v3 - mu) * rs * g4.w + b4.w;
    *(float4*)(out + base + c) = o;
}

// ---------------- V transpose: Vt hi/lo bf16 [bh][64][2048] into g_tmp ----------------
__global__ __launch_bounds__(256)
void vt_kernel() {
    extern __shared__ float tile[];  // [64][129]
    const int bh = blockIdx.y, b = bh >> 3, h = bh & 7;
    const int s0 = blockIdx.x * 128;
    const float* vb = g_qkv + b * QKV_LD + 2 * EMBED + h * HD;
    const int tid = threadIdx.x;
    for (int i = tid; i < 2048; i += 256) {
        int r = i >> 4, c4 = (i & 15) * 4;
        float4 v = *(const float4*)(vb + (size_t)(s0 + r) * ROWSTRIDE + c4);
        tile[(c4 + 0) * 129 + r] = v.x;
        tile[(c4 + 1) * 129 + r] = v.y;
        tile[(c4 + 2) * 129 + r] = v.z;
        tile[(c4 + 3) * 129 + r] = v.w;
    }
    __syncthreads();
    __nv_bfloat16* Vth = (__nv_bfloat16*)g_tmp;
    __nv_bfloat16* Vtl = Vth + (size_t)BH * 64 * 2048;
    for (int i = tid; i < 2048; i += 256) {
        int d = i >> 5, s4 = (i & 31) * 4;
        float4 v;
        v.x = tile[d * 129 + s4 + 0];
        v.y = tile[d * 129 + s4 + 1];
        v.z = tile[d * 129 + s4 + 2];
        v.w = tile[d * 129 + s4 + 3];
        uint2 uh, ul;
        cvt4(v, uh, ul);
        size_t off = (size_t)bh * 64 * 2048 + (size_t)d * 2048 + s0 + s4;
        *(uint2*)(Vth + off) = uh;
        *(uint2*)(Vtl + off) = ul;
    }
}

// ---------------- mma linear: C[M,N] = A@B^T + bias (opt relu) ----------------
__global__ __launch_bounds__(256)
void mma_linear(const float* __restrict__ Aq, const float* __restrict__ Akv, int nsplit,
                const float* __restrict__ Bw, const float* __restrict__ bias,
                float* __restrict__ C, int N, int K, int relu) {
    extern __shared__ char dyn[];
    __nv_bfloat16* sAh = (__nv_bfloat16*)dyn;
    __nv_bfloat16* sAl = sAh + 128 * S32;
    __nv_bfloat16* sBh = sAl + 128 * S32;
    __nv_bfloat16* sBl = sBh + 128 * S32;
    const int tid = threadIdx.x, wid = tid >> 5, lane = tid & 31;
    const int bn = blockIdx.x * 128, bm = blockIdx.y * 128;
    const float* A = (bn < nsplit) ? Aq : Akv;
    const int wm = (wid >> 2) * 64, wn = (wid & 3) * 32;
    const uint32_t uAh = smem_u32(sAh), uAl = smem_u32(sAl);
    const uint32_t uBh = smem_u32(sBh), uBl = smem_u32(sBl);

    float acc[4][4][4] = {};
    const int nkt = K >> 5;
    for (int kt = 0; kt < nkt; kt++) {
        for (int i = tid; i < 1024; i += 256) {
            int r = i >> 3, c4 = (i & 7) * 4;
            uint2 uh, ul;
            cvt4(*(const float4*)(A + (size_t)(bm + r) * K + kt * 32 + c4), uh, ul);
            *(uint2*)(sAh + r * S32 + c4) = uh;
            *(uint2*)(sAl + r * S32 + c4) = ul;
        }
        for (int i = tid; i < 1024; i += 256) {
            int r = i >> 3, c4 = (i & 7) * 4;
            uint2 uh, ul;
            cvt4(*(const float4*)(Bw + (size_t)(bn + r) * K + kt * 32 + c4), uh, ul);
            *(uint2*)(sBh + r * S32 + c4) = uh;
            *(uint2*)(sBl + r * S32 + c4) = ul;
        }
        __syncthreads();
#pragma unroll
        for (int ks = 0; ks < 2; ks++) {
            uint32_t ah[4][4], al[4][4], bh[2][4], bl[2][4];
#pragma unroll
            for (int i = 0; i < 4; i++) {
                uint32_t off = ((wm + i * 16 + (lane & 15)) * S32 + ks * 16 + (lane >> 4) * 8) * 2;
                ldmx4(ah[i], uAh + off);
                ldmx4(al[i], uAl + off);
            }
#pragma unroll
            for (int j2 = 0; j2 < 2; j2++) {
                uint32_t off = ((wn + j2 * 16 + ((lane >> 4) & 1) * 8 + (lane & 7)) * S32
                               + ks * 16 + ((lane >> 3) & 1) * 8) * 2;
                ldmx4(bh[j2], uBh + off);
                ldmx4(bl[j2], uBl + off);
            }
#pragma unroll
            for (int i = 0; i < 4; i++)
#pragma unroll
                for (int j = 0; j < 4; j++) {
                    const uint32_t* bhf = &bh[j >> 1][(j & 1) * 2];
                    const uint32_t* blf = &bl[j >> 1][(j & 1) * 2];
                    mma16816(acc[i][j], ah[i], bhf);
                    mma16816(acc[i][j], al[i], bhf);
                    mma16816(acc[i][j], ah[i], blf);
                }
        }
        __syncthreads();
    }
#pragma unroll
    for (int i = 0; i < 4; i++) {
        const int m0 = bm + wm + i * 16 + (lane >> 2);
#pragma unroll
        for (int j = 0; j < 4; j++) {
            const int n0 = bn + wn + j * 8 + (lane & 3) * 2;
            float b0 = bias[n0], b1 = bias[n0 + 1];
            float2 o0, o1;
            o0.x = acc[i][j][0] + b0; o0.y = acc[i][j][1] + b1;
            o1.x = acc[i][j][2] + b0; o1.y = acc[i][j][3] + b1;
            if (relu) {
                o0.x = fmaxf(o0.x, 0.f); o0.y = fmaxf(o0.y, 0.f);
                o1.x = fmaxf(o1.x, 0.f); o1.y = fmaxf(o1.y, 0.f);
            }
            *(float2*)(C + (size_t)m0 * N + n0) = o0;
            *(float2*)(C + (size_t)(m0 + 8) * N + n0) = o1;
        }
    }
}

// ---------------- scores: W(hi/lo bf16) = mask(Q.K^T*scale), fused min/max ----------------
__global__ __launch_bounds__(256)
void mma_scores(int selfmask) {
    const int bh = blockIdx.z, b = bh >> 3, h = bh & 7;
    const int bs = blockIdx.x * 128, bt = blockIdx.y * 128;
    if (selfmask && bs > bt) return;
    extern __shared__ char dyn[];
    __nv_bfloat16* sAh = (__nv_bfloat16*)dyn;
    __nv_bfloat16* sAl = sAh + 128 * S64;
    __nv_bfloat16* sBh = sAl + 128 * S64;
    __nv_bfloat16* sBl = sBh + 128 * S64;
    const int tid = threadIdx.x, wid = tid >> 5, lane = tid & 31;
    const int wm = (wid >> 2) * 64, wn = (wid & 3) * 32;
    const float* qb = g_qkv + b * QKV_LD + h * HD;
    const float* kb = g_qkv + b * QKV_LD + EMBED + h * HD;

    for (int i = tid; i < 2048; i += 256) {
        int r = i >> 4, c4 = (i & 15) * 4;
        uint2 uh, ul;
        cvt4(*(const float4*)(qb + (size_t)(bt + r) * ROWSTRIDE + c4), uh, ul);
        *(uint2*)(sAh + r * S64 + c4) = uh;
        *(uint2*)(sAl + r * S64 + c4) = ul;
    }
    for (int i = tid; i < 2048; i += 256) {
        int r = i >> 4, c4 = (i & 15) * 4;
        uint2 uh, ul;
        cvt4(*(const float4*)(kb + (size_t)(bs + r) * ROWSTRIDE + c4), uh, ul);
        *(uint2*)(sBh + r * S64 + c4) = uh;
        *(uint2*)(sBl + r * S64 + c4) = ul;
    }
    __syncthreads();

    const uint32_t uAh = smem_u32(sAh), uAl = smem_u32(sAl);
    const uint32_t uBh = smem_u32(sBh), uBl = smem_u32(sBl);
    float acc[4][4][4] = {};
#pragma unroll
    for (int ks = 0; ks < 4; ks++) {
        uint32_t ah[4][4], al[4][4], bh[2][4], bl[2][4];
#pragma unroll
        for (int i = 0; i < 4; i++) {
            uint32_t off = ((wm + i * 16 + (lane & 15)) * S64 + ks * 16 + (lane >> 4) * 8) * 2;
            ldmx4(ah[i], uAh + off);
            ldmx4(al[i], uAl + off);
        }
#pragma unroll
        for (int j2 = 0; j2 < 2; j2++) {
            uint32_t off = ((wn + j2 * 16 + ((lane >> 4) & 1) * 8 + (lane & 7)) * S64
                           + ks * 16 + ((lane >> 3) & 1) * 8) * 2;
            ldmx4(bh[j2], uBh + off);
            ldmx4(bl[j2], uBl + off);
        }
#pragma unroll
        for (int i = 0; i < 4; i++)
#pragma unroll
            for (int j = 0; j < 4; j++) {
                const uint32_t* bhf = &bh[j >> 1][(j & 1) * 2];
                const uint32_t* blf = &bl[j >> 1][(j & 1) * 2];
                mma16816(acc[i][j], ah[i], bhf);
                mma16816(acc[i][j], al[i], bhf);
                mma16816(acc[i][j], ah[i], blf);
            }
    }

    __nv_bfloat16* Whi = (__nv_bfloat16*)g_W;
    __nv_bfloat16* Wlo = Whi + BH * TT;
    float lmin = 3.4e38f, lmax = -3.4e38f;
#pragma unroll
    for (int i = 0; i < 4; i++) {
        const int t0 = bt + wm + i * 16 + (lane >> 2);
#pragma unroll
        for (int j = 0; j < 4; j++) {
            const int s = bs + wn + j * 8 + (lane & 3) * 2;
#pragma unroll
            for (int half = 0; half < 2; half++) {
                const int t = t0 + half * 8;
                float v0 = acc[i][j][half * 2 + 0] * 0.125f;
                float v1 = acc[i][j][half * 2 + 1] * 0.125f;
                if (selfmask) {
                    if (s + 0 > t) v0 = 0.f;
                    if (s + 1 > t) v1 = 0.f;
                }
                lmin = fminf(lmin, fminf(v0, v1));
                lmax = fmaxf(lmax, fmaxf(v0, v1));
                __nv_bfloat162 hh = __floats2bfloat162_rn(v0, v1);
                float2 hf = __bfloat1622float2(hh);
                __nv_bfloat162 ll = __floats2bfloat162_rn(v0 - hf.x, v1 - hf.y);
                size_t off = (size_t)bh * TT + (size_t)t * T_SEQ + s;
                *(uint32_t*)(Whi + off) = *(uint32_t*)&hh;
                *(uint32_t*)(Wlo + off) = *(uint32_t*)&ll;
            }
        }
    }
#pragma unroll
    for (int off = 16; off > 0; off >>= 1) {
        lmin = fminf(lmin, __shfl_xor_sync(0xffffffffu, lmin, off));
        lmax = fmaxf(lmax, __shfl_xor_sync(0xffffffffu, lmax, off));
    }
    __shared__ float rmn[8], rmx[8];
    if (lane == 0) { rmn[wid] = lmin; rmx[wid] = lmax; }
    __syncthreads();
    if (tid == 0) {
        float mn = rmn[0], mx = rmx[0];
#pragma unroll
        for (int w = 1; w < 8; w++) { mn = fminf(mn, rmn[w]); mx = fmaxf(mx, rmx[w]); }
        atomicMin(&g_minmax[0], fenc(mn));
        atomicMax(&g_minmax[1], fenc(mx));
    }
}

// ---------------- AV: a = (W@V - mn*Vsum) / (mx - mn) ----------------
__global__ __launch_bounds__(256)
void mma_av(int selfmask) {
    const int bh = blockIdx.z, b = bh >> 3, h = bh & 7;
    const int bm = blockIdx.y * 128;
    extern __shared__ char dyn[];
    __nv_bfloat16* sAh = (__nv_bfloat16*)dyn;           // 128 x S32
    __nv_bfloat16* sAl = sAh + 128 * S32;
    __nv_bfloat16* sBh = sAl + 128 * S32;               // 64 x S32
    __nv_bfloat16* sBl = sBh + 64 * S32;
    const int tid = threadIdx.x, wid = tid >> 5, lane = tid & 31;
    const int wm = (wid >> 1) * 32, wn = (wid & 1) * 32;
    const __nv_bfloat16* Whi = (const __nv_bfloat16*)g_W;
    const __nv_bfloat16* Wlo = Whi + BH * TT;
    const __nv_bfloat16* Vth = (const __nv_bfloat16*)g_tmp;
    const __nv_bfloat16* Vtl = Vth + (size_t)BH * 64 * 2048;
    const size_t wbase = (size_t)bh * TT + (size_t)bm * T_SEQ;
    const size_t vbase = (size_t)bh * 64 * 2048;
    const uint32_t uAh = smem_u32(sAh), uAl = smem_u32(sAl);
    const uint32_t uBh = smem_u32(sBh), uBl = smem_u32(sBl);

    float acc[2][4][4] = {};
    const int nkt = selfmask ? (bm / 32 + 4) : 64;
    for (int kt = 0; kt < nkt; kt++) {
        for (int i = tid; i < 1024; i += 256) {
            int r = i >> 3, q = (i & 7) * 4;
            size_t so = wbase + (size_t)r * T_SEQ + kt * 32 + q;
            *(uint2*)(sAh + r * S32 + q) = *(const uint2*)(Whi + so);
            *(uint2*)(sAl + r * S32 + q) = *(const uint2*)(Wlo + so);
        }
        for (int i = tid; i < 512; i += 256) {
            int r = i >> 3, q = (i & 7) * 4;
            size_t so = vbase + (size_t)r * 2048 + kt * 32 + q;
            *(uint2*)(sBh + r * S32 + q) = *(const uint2*)(Vth + so);
            *(uint2*)(sBl + r * S32 + q) = *(const uint2*)(Vtl + so);
        }
        __syncthreads();
#pragma unroll
        for (int ks = 0; ks < 2; ks++) {
            uint32_t ah[2][4], al[2][4], bh[2][4], bl[2][4];
#pragma unroll
            for (int i = 0; i < 2; i++) {
                uint32_t off = ((wm + i * 16 + (lane & 15)) * S32 + ks * 16 + (lane >> 4) * 8) * 2;
                ldmx4(ah[i], uAh + off);
                ldmx4(al[i], uAl + off);
            }
#pragma unroll
            for (int j2 = 0; j2 < 2; j2++) {
                uint32_t off = ((wn + j2 * 16 + ((lane >> 4) & 1) * 8 + (lane & 7)) * S32
                               + ks * 16 + ((lane >> 3) & 1) * 8) * 2;
                ldmx4(bh[j2], uBh + off);
                ldmx4(bl[j2], uBl + off);
            }
#pragma unroll
            for (int i = 0; i < 2; i++)
#pragma unroll
                for (int j = 0; j < 4; j++) {
                    const uint32_t* bhf = &bh[j >> 1][(j & 1) * 2];
                    const uint32_t* blf = &bl[j >> 1][(j & 1) * 2];
                    mma16816(acc[i][j], ah[i], bhf);
                    mma16816(acc[i][j], al[i], bhf);
                    mma16816(acc[i][j], ah[i], blf);
                }
        }
        __syncthreads();
    }

    const float mn = fdec(g_minmax[0]);
    const float mx = fdec(g_minmax[1]);
    const float inv = 1.f / (mx - mn);
#pragma unroll
    for (int i = 0; i < 2; i++) {
        const int t0 = bm + wm + i * 16 + (lane >> 2);
#pragma unroll
        for (int j = 0; j < 4; j++) {
            const int d = wn + j * 8 + (lane & 3) * 2;
            float vs0 = g_vsum[bh * 64 + d], vs1 = g_vsum[bh * 64 + d + 1];
#pragma unroll
            for (int half = 0; half < 2; half++) {
                const int t = t0 + half * 8;
                float2 o;
                o.x = (acc[i][j][half * 2 + 0] - mn * vs0) * inv;
                o.y = (acc[i][j][half * 2 + 1] - mn * vs1) * inv;
                *(float2*)(g_attn + (size_t)(t * BATCH + b) * EMBED + h * HD + d) = o;
            }
        }
    }
}

// ---------------- host orchestration ----------------
extern "C" void kernel_launch(void* const* d_in, const int* in_sizes, int n_in,
                              void* d_out, int out_size) {
    const float* x         = (const float*)d_in[0];
    const float* enc_out   = (const float*)d_in[1];
    const int*   tokens    = (const int*)d_in[2];
    const float* self_Wqkv = (const float*)d_in[3];
    const float* self_bqkv = (const float*)d_in[4];
    const float* self_Wo   = (const float*)d_in[5];
    const float* self_bo   = (const float*)d_in[6];
    const float* cross_Wqkv= (const float*)d_in[7];
    const float* cross_bqkv= (const float*)d_in[8];
    const float* cross_Wo  = (const float*)d_in[9];
    const float* cross_bo  = (const float*)d_in[10];
    const float* fc1_w     = (const float*)d_in[11];
    const float* fc1_b     = (const float*)d_in[12];
    const float* fc2_w     = (const float*)d_in[13];
    const float* fc2_b     = (const float*)d_in[14];
    const float* ln1_g     = (const float*)d_in[15];
    const float* ln1_b     = (const float*)d_in[16];
    const float* ln2_g     = (const float*)d_in[17];
    const float* ln2_b     = (const float*)d_in[18];
    const float* ln3_g     = (const float*)d_in[19];
    const float* ln3_b     = (const float*)d_in[20];

    float *px, *pqkv, *pattn, *ptmp;
    cudaGetSymbolAddress((void**)&px, g_x);
    cudaGetSymbolAddress((void**)&pqkv, g_qkv);
    cudaGetSymbolAddress((void**)&pattn, g_attn);
    cudaGetSymbolAddress((void**)&ptmp, g_tmp);

    const int SM_LIN = 4 * 128 * S32 * 2;              // 40960
    const int SM_SCO = 4 * 128 * S64 * 2;              // 73728
    const int SM_AV  = 2 * 128 * S32 * 2 + 2 * 64 * S32 * 2;  // 30720
    const int SM_VT  = 64 * 129 * 4;                   // 33024
    cudaFuncSetAttribute(mma_scores, cudaFuncAttributeMaxDynamicSharedMemorySize, SM_SCO);
    cudaFuncSetAttribute(mma_linear, cudaFuncAttributeMaxDynamicSharedMemorySize, SM_LIN);
    cudaFuncSetAttribute(mma_av, cudaFuncAttributeMaxDynamicSharedMemorySize, SM_AV);
    cudaFuncSetAttribute(vt_kernel, cudaFuncAttributeMaxDynamicSharedMemorySize, SM_VT);

    const int BIG = 1 << 30;

    posembed_kernel<<<(NROWS * EMBED) / 256, 256>>>(x, tokens, px);

    for (int l = 0; l < 4; l++) {
        // ---- self attention ----
        minmax_init_kernel<<<1, 1>>>(1);
        mma_linear<<<dim3(12, 32), 256, SM_LIN>>>(px, px, BIG,
            self_Wqkv + (size_t)l * QKV_LD * EMBED, self_bqkv + l * QKV_LD,
            pqkv, QKV_LD, EMBED, 0);
        mma_scores<<<dim3(16, 16, 16), 256, SM_SCO>>>(1);
        vsum_kernel<<<16, 256>>>();
        vt_kernel<<<dim3(16, 16), 256, SM_VT>>>();
        mma_av<<<dim3(1, 16, 16), 256, SM_AV>>>(1);
        mma_linear<<<dim3(4, 32), 256, SM_LIN>>>(pattn, pattn, BIG,
            self_Wo + (size_t)l * EMBED * EMBED, self_bo + l * EMBED,
            ptmp, EMBED, EMBED, 0);
        ln_kernel<<<NROWS, 128>>>(px, ptmp, ln1_g + l * EMBED, ln1_b + l * EMBED, px);

        // ---- cross attention ----
        minmax_init_kernel<<<1, 1>>>(0);
        mma_linear<<<dim3(12, 32), 256, SM_LIN>>>(px, enc_out, EMBED,
            cross_Wqkv + (size_t)l * QKV_LD * EMBED, cross_bqkv + l * QKV_LD,
            pqkv, QKV_LD, EMBED, 0);
        mma_scores<<<dim3(16, 16, 16), 256, SM_SCO>>>(0);
        vsum_kernel<<<16, 256>>>();
        vt_kernel<<<dim3(16, 16), 256, SM_VT>>>();
        mma_av<<<dim3(1, 16, 16), 256, SM_AV>>>(0);
        mma_linear<<<dim3(4, 32), 256, SM_LIN>>>(pattn, pattn, BIG,
            cross_Wo + (size_t)l * EMBED * EMBED, cross_bo + l * EMBED,
            ptmp, EMBED, EMBED, 0);
        ln_kernel<<<NROWS, 128>>>(px, ptmp, ln2_g + l * EMBED, ln2_b + l * EMBED, px);

        // ---- FFN ----
        mma_linear<<<dim3(16, 32), 256, SM_LIN>>>(px, px, BIG,
            fc1_w + (size_t)l * FFN_DIM * EMBED, fc1_b + l * FFN_DIM,
            ptmp, FFN_DIM, EMBED, 1);
        mma_linear<<<dim3(4, 32), 256, SM_LIN>>>(ptmp, ptmp, BIG,
            fc2_w + (size_t)l * EMBED * FFN_DIM, fc2_b + l * EMBED,
            pattn, EMBED, FFN_DIM, 0);
        float* lnout = (l == 3) ? (float*)d_out : px;
        ln_kernel<<<NROWS, 128>>>(px, pattn, ln3_g + l * EMBED, ln3_b + l * EMBED, lnout);
    }
}

// round 5
// speedup vs baseline: 2.3133x; 1.7126x over previous
#include <cuda_runtime.h>
#include <cuda_bf16.h>
#include <cstdint>

#define T_SEQ 2048
#define BATCH 2
#define EMBED 512
#define NHEADS 8
#define HD 64
#define FFN_DIM 2048
#define NROWS (T_SEQ * BATCH)      // 4096
#define BH (BATCH * NHEADS)        // 16
#define QKV_LD (3 * EMBED)         // 1536
#define ROWSTRIDE (BATCH * QKV_LD) // 3072 (elem stride between consecutive t)
#define TT ((size_t)T_SEQ * T_SEQ)
#define S32 40
#define S64 72

// weight-plane segment offsets (elems)
#define S_SQKV 0
#define S_SWO  3145728
#define S_CQKV 4194304
#define S_CWO  7340032
#define S_FC1  8388608
#define S_FC2  12582912
#define W_TOT  16777216

// ---------------- device scratch ----------------
__device__ __align__(16) float g_x[NROWS * EMBED];
__device__ __align__(16) float g_y[NROWS * EMBED];
__device__ __align__(16) float g_W[BH * TT];          // 2 bf16 planes hi|lo inside
__device__ __align__(16) __nv_bfloat16 g_xh[NROWS * EMBED], g_xl[NROWS * EMBED];
__device__ __align__(16) __nv_bfloat16 g_ench[NROWS * EMBED], g_encl[NROWS * EMBED];
__device__ __align__(16) __nv_bfloat16 g_qkvh[NROWS * QKV_LD], g_qkvl[NROWS * QKV_LD];
__device__ __align__(16) __nv_bfloat16 g_vth[BH * 64 * 2048], g_vtl[BH * 64 * 2048];
__device__ __align__(16) __nv_bfloat16 g_hidh[NROWS * FFN_DIM], g_hidl[NROWS * FFN_DIM];
__device__ __align__(16) __nv_bfloat16 g_ah[NROWS * EMBED], g_al[NROWS * EMBED];
__device__ __align__(16) __nv_bfloat16 g_wbh[W_TOT], g_wbl[W_TOT];
__device__ float g_vsum[BH * HD];
__device__ unsigned g_minmax[2];

__device__ __forceinline__ unsigned fenc(float f) {
    unsigned u = __float_as_uint(f);
    return (u & 0x80000000u) ? ~u : (u | 0x80000000u);
}
__device__ __forceinline__ float fdec(unsigned e) {
    return __uint_as_float((e & 0x80000000u) ? (e ^ 0x80000000u) : ~e);
}
__device__ __forceinline__ uint32_t smem_u32(const void* p) {
    uint32_t a;
    asm("{ .reg .u64 t; cvta.to.shared.u64 t, %1; cvt.u32.u64 %0, t; }" : "=r"(a) : "l"(p));
    return a;
}
__device__ __forceinline__ void cpa16(uint32_t d, const void* s) {
    asm volatile("cp.async.cg.shared.global [%0], [%1], 16;" :: "r"(d), "l"(s));
}
#define CPA_COMMIT() asm volatile("cp.async.commit_group;" ::: "memory")
#define CPA_WAIT0()  asm volatile("cp.async.wait_group 0;" ::: "memory")
#define CPA_WAIT1()  asm volatile("cp.async.wait_group 1;" ::: "memory")

__device__ __forceinline__ void ldmx4(uint32_t* r, uint32_t addr) {
    asm volatile("ldmatrix.sync.aligned.m8n8.x4.shared.b16 {%0,%1,%2,%3}, [%4];"
        : "=r"(r[0]), "=r"(r[1]), "=r"(r[2]), "=r"(r[3]) : "r"(addr));
}
__device__ __forceinline__ void mma16816(float* c, const uint32_t* a, const uint32_t* b) {
    asm volatile("mma.sync.aligned.m16n8k16.row.col.f32.bf16.bf16.f32 "
        "{%0,%1,%2,%3}, {%4,%5,%6,%7}, {%8,%9}, {%0,%1,%2,%3};"
        : "+f"(c[0]), "+f"(c[1]), "+f"(c[2]), "+f"(c[3])
        : "r"(a[0]), "r"(a[1]), "r"(a[2]), "r"(a[3]), "r"(b[0]), "r"(b[1]));
}
__device__ __forceinline__ void cvt4(float4 v, uint2& uh, uint2& ul) {
    __nv_bfloat162 h01 = __floats2bfloat162_rn(v.x, v.y);
    __nv_bfloat162 h23 = __floats2bfloat162_rn(v.z, v.w);
    float2 f01 = __bfloat1622float2(h01);
    float2 f23 = __bfloat1622float2(h23);
    __nv_bfloat162 l01 = __floats2bfloat162_rn(v.x - f01.x, v.y - f01.y);
    __nv_bfloat162 l23 = __floats2bfloat162_rn(v.z - f23.x, v.w - f23.y);
    uh.x = *(uint32_t*)&h01; uh.y = *(uint32_t*)&h23;
    ul.x = *(uint32_t*)&l01; ul.y = *(uint32_t*)&l23;
}
__device__ __forceinline__ void cvt2(float v0, float v1, uint32_t& h, uint32_t& l) {
    __nv_bfloat162 hh = __floats2bfloat162_rn(v0, v1);
    float2 hf = __bfloat1622float2(hh);
    __nv_bfloat162 ll = __floats2bfloat162_rn(v0 - hf.x, v1 - hf.y);
    h = *(uint32_t*)&hh; l = *(uint32_t*)&ll;
}

// ---------------- small kernels ----------------
__global__ void minmax_init_kernel(int selfmask) {
    if (selfmask) { g_minmax[0] = fenc(0.f); g_minmax[1] = fenc(0.f); }
    else          { g_minmax[0] = 0xFFFFFFFFu; g_minmax[1] = 0u; }
}

__global__ void cvt_planes(const float* __restrict__ src,
                           __nv_bfloat16* __restrict__ dh,
                           __nv_bfloat16* __restrict__ dl, int n4) {
    int i = blockIdx.x * 256 + threadIdx.x;
    if (i >= n4) return;
    float4 v = ((const float4*)src)[i];
    uint2 uh, ul;
    cvt4(v, uh, ul);
    ((uint2*)dh)[i] = uh;
    ((uint2*)dl)[i] = ul;
}

__global__ void posembed_kernel(const float* __restrict__ x,
                                const int* __restrict__ tokens) {
    int i = blockIdx.x * 256 + threadIdx.x;  // NROWS*EMBED/4
    int c4 = (i & 127) * 4;
    int row = i >> 7;
    int t = row >> 1, b = row & 1;
    int tok = tokens[b * T_SEQ + t];
    float4 v = ((const float4*)x)[i];
    if (tok != 0) {
        float p = (float)(t + 1);
        float* pv = (float*)&v;
#pragma unroll
        for (int e = 0; e < 4; e++) {
            int c = c4 + e;
            int ii = (c < 256) ? c : c - 256;
            float ang = p * expf((float)ii * (-9.210340371976184f / 255.0f));
            pv[e] += (c < 256) ? sinf(ang) : cosf(ang);
        }
    }
    ((float4*)g_x)[i] = v;
    uint2 uh, ul;
    cvt4(v, uh, ul);
    ((uint2*)g_xh)[i] = uh;
    ((uint2*)g_xl)[i] = ul;
}

__global__ void vsum_kernel() {
    const int bh = blockIdx.x;
    const int b = bh >> 3, h = bh & 7;
    const __nv_bfloat16* vh = g_qkvh + b * QKV_LD + 2 * EMBED + h * HD;
    const __nv_bfloat16* vl = g_qkvl + b * QKV_LD + 2 * EMBED + h * HD;
    const int d = threadIdx.x & 63;
    const int part = threadIdx.x >> 6;
    float s = 0.f;
    for (int i = part * 512; i < part * 512 + 512; i++) {
        size_t off = (size_t)i * ROWSTRIDE + d;
        s += __bfloat162float(vh[off]) + __bfloat162float(vl[off]);
    }
    __shared__ float sm[256];
    sm[threadIdx.x] = s;
    __syncthreads();
    if (threadIdx.x < 64)
        g_vsum[bh * 64 + d] = sm[d] + sm[64 + d] + sm[128 + d] + sm[192 + d];
}

__global__ void ln_kernel(const float* __restrict__ res, const float* __restrict__ y,
                          const float* __restrict__ gam, const float* __restrict__ bet,
                          float* __restrict__ out,
                          __nv_bfloat16* __restrict__ outh, __nv_bfloat16* __restrict__ outl) {
    const int row = blockIdx.x;
    const int tid = threadIdx.x;
    const size_t base = (size_t)row * EMBED;
    float4 r4 = *(const float4*)(res + base + tid * 4);
    float4 y4 = *(const float4*)(y + base + tid * 4);
    float v0 = r4.x + y4.x, v1 = r4.y + y4.y, v2 = r4.z + y4.z, v3 = r4.w + y4.w;
    float s = v0 + v1 + v2 + v3;
    float q = v0 * v0 + v1 * v1 + v2 * v2 + v3 * v3;
#pragma unroll
    for (int off = 16; off > 0; off >>= 1) {
        s += __shfl_down_sync(0xffffffffu, s, off);
        q += __shfl_down_sync(0xffffffffu, q, off);
    }
    __shared__ float sm[8];
    __shared__ float stats[2];
    const int wid = tid >> 5, lane = tid & 31;
    if (lane == 0) { sm[wid] = s; sm[4 + wid] = q; }
    __syncthreads();
    if (tid == 0) {
        float S = sm[0] + sm[1] + sm[2] + sm[3];
        float Q = sm[4] + sm[5] + sm[6] + sm[7];
        float mu = S * (1.f / 512.f);
        float var = Q * (1.f / 512.f) - mu * mu;
        stats[0] = mu;
        stats[1] = rsqrtf(fmaxf(var, 0.f) + 1e-20f);
    }
    __syncthreads();
    const float mu = stats[0], rs = stats[1];
    const int c = tid * 4;
    float4 g4 = *(const float4*)(gam + c);
    float4 b4 = *(const float4*)(bet + c);
    float4 o;
    o.x = (v0 - mu) * rs * g4.x + b4.x;
    o.y = (v1 - mu) * rs * g4.y + b4.y;
    o.z = (v2 - mu) * rs * g4.z + b4.z;
    o.w = (v3 - mu) * rs * g4.w + b4.w;
    *(float4*)(out + base + c) = o;
    uint2 uh, ul;
    cvt4(o, uh, ul);
    *(uint2*)(outh + base + c) = uh;
    *(uint2*)(outl + base + c) = ul;
}

// ---------------- V transpose (bf16 planes -> Vt planes) ----------------
// NOTE: row stride 132 elems = 264 bytes (multiple of 8) so uint2 reads of
// &th[d][s4] are aligned for all d. (130 was the Round-4 misaligned-address bug.)
__global__ __launch_bounds__(256)
void vt_kernel() {
    __shared__ __nv_bfloat16 th[64][132], tl[64][132];
    const int bh = blockIdx.y, b = bh >> 3, h = bh & 7;
    const int s0 = blockIdx.x * 128;
    const __nv_bfloat16* vh = g_qkvh + b * QKV_LD + 2 * EMBED + h * HD;
    const __nv_bfloat16* vl = g_qkvl + b * QKV_LD + 2 * EMBED + h * HD;
    const int tid = threadIdx.x;
    for (int i = tid; i < 2048; i += 256) {
        int r = i >> 4, q = (i & 15) * 4;
        size_t off = (size_t)(s0 + r) * ROWSTRIDE + q;
        uint2 ah = *(const uint2*)(vh + off);
        uint2 al = *(const uint2*)(vl + off);
        __nv_bfloat16* ph = (__nv_bfloat16*)&ah;
        __nv_bfloat16* pl = (__nv_bfloat16*)&al;
#pragma unroll
        for (int e = 0; e < 4; e++) { th[q + e][r] = ph[e]; tl[q + e][r] = pl[e]; }
    }
    __syncthreads();
    for (int i = tid; i < 2048; i += 256) {
        int d = i >> 5, s4 = (i & 31) * 4;
        size_t off = (size_t)bh * 64 * 2048 + (size_t)d * 2048 + s0 + s4;
        *(uint2*)(g_vth + off) = *(uint2*)&th[d][s4];
        *(uint2*)(g_vtl + off) = *(uint2*)&tl[d][s4];
    }
}

// ---------------- mma linear (bf16 planes in, cp.async 2-stage) ----------------
// C = A@B^T + bias; mode 0: fp32 out; 1: bf16 planes out; 2: planes + relu
#define LIN_STG 40960
__global__ __launch_bounds__(256)
void mma_linear(const __nv_bfloat16* __restrict__ Aqh, const __nv_bfloat16* __restrict__ Aql,
                const __nv_bfloat16* __restrict__ Akvh, const __nv_bfloat16* __restrict__ Akvl,
                int nsplit,
                const __nv_bfloat16* __restrict__ Bh, const __nv_bfloat16* __restrict__ Bl,
                const float* __restrict__ bias, int N, int K, int mode,
                float* __restrict__ Cf, __nv_bfloat16* __restrict__ Ch,
                __nv_bfloat16* __restrict__ Cl) {
    extern __shared__ char dyn[];
    const uint32_t u0 = smem_u32(dyn);
    const int tid = threadIdx.x, wid = tid >> 5, lane = tid & 31;
    const int bn = blockIdx.x * 128, bm = blockIdx.y * 128;
    const __nv_bfloat16* Ah = (bn < nsplit) ? Aqh : Akvh;
    const __nv_bfloat16* Al = (bn < nsplit) ? Aql : Akvl;
    const int wm = (wid >> 2) * 64, wn = (wid & 3) * 32;

    float acc[4][4][4] = {};
    const int nkt = K >> 5;

    // prologue load kt=0 into stage 0
#pragma unroll 1
    for (int i = tid; i < 512; i += 256) {
        int r = i >> 2, c = (i & 3) * 8;
        uint32_t d = u0 + (r * S32 + c) * 2;
        cpa16(d,         Ah + (size_t)(bm + r) * K + c);
        cpa16(d + 10240, Al + (size_t)(bm + r) * K + c);
        cpa16(d + 20480, Bh + (size_t)(bn + r) * K + c);
        cpa16(d + 30720, Bl + (size_t)(bn + r) * K + c);
    }
    CPA_COMMIT();

    for (int kt = 0; kt < nkt; kt++) {
        const uint32_t sb = u0 + (kt & 1) * LIN_STG;
        if (kt + 1 < nkt) {
            const uint32_t nb = u0 + ((kt + 1) & 1) * LIN_STG;
            const int kc = (kt + 1) * 32;
#pragma unroll 1
            for (int i = tid; i < 512; i += 256) {
                int r = i >> 2, c = (i & 3) * 8;
                uint32_t d = nb + (r * S32 + c) * 2;
                cpa16(d,         Ah + (size_t)(bm + r) * K + kc + c);
                cpa16(d + 10240, Al + (size_t)(bm + r) * K + kc + c);
                cpa16(d + 20480, Bh + (size_t)(bn + r) * K + kc + c);
                cpa16(d + 30720, Bl + (size_t)(bn + r) * K + kc + c);
            }
            CPA_COMMIT();
            CPA_WAIT1();
        } else {
            CPA_WAIT0();
        }
        __syncthreads();
#pragma unroll
        for (int ks = 0; ks < 2; ks++) {
            uint32_t ah[4][4], al[4][4], bh[2][4], bl[2][4];
#pragma unroll
            for (int i = 0; i < 4; i++) {
                uint32_t off = sb + ((wm + i * 16 + (lane & 15)) * S32 + ks * 16 + (lane >> 4) * 8) * 2;
                ldmx4(ah[i], off);
                ldmx4(al[i], off + 10240);
            }
#pragma unroll
            for (int j2 = 0; j2 < 2; j2++) {
                uint32_t off = sb + ((wn + j2 * 16 + ((lane >> 4) & 1) * 8 + (lane & 7)) * S32
                               + ks * 16 + ((lane >> 3) & 1) * 8) * 2;
                ldmx4(bh[j2], off + 20480);
                ldmx4(bl[j2], off + 30720);
            }
#pragma unroll
            for (int i = 0; i < 4; i++)
#pragma unroll
                for (int j = 0; j < 4; j++) {
                    const uint32_t* bhf = &bh[j >> 1][(j & 1) * 2];
                    const uint32_t* blf = &bl[j >> 1][(j & 1) * 2];
                    mma16816(acc[i][j], ah[i], bhf);
                    mma16816(acc[i][j], al[i], bhf);
                    mma16816(acc[i][j], ah[i], blf);
                }
        }
        __syncthreads();
    }
#pragma unroll
    for (int i = 0; i < 4; i++) {
        const int m0 = bm + wm + i * 16 + (lane >> 2);
#pragma unroll
        for (int j = 0; j < 4; j++) {
            const int n0 = bn + wn + j * 8 + (lane & 3) * 2;
            float b0 = bias[n0], b1 = bias[n0 + 1];
#pragma unroll
            for (int half = 0; half < 2; half++) {
                const int m = m0 + half * 8;
                float v0 = acc[i][j][half * 2 + 0] + b0;
                float v1 = acc[i][j][half * 2 + 1] + b1;
                if (mode == 2) { v0 = fmaxf(v0, 0.f); v1 = fmaxf(v1, 0.f); }
                if (mode == 0) {
                    float2 o = make_float2(v0, v1);
                    *(float2*)(Cf + (size_t)m * N + n0) = o;
                } else {
                    uint32_t h, l;
                    cvt2(v0, v1, h, l);
                    *(uint32_t*)(Ch + (size_t)m * N + n0) = h;
                    *(uint32_t*)(Cl + (size_t)m * N + n0) = l;
                }
            }
        }
    }
}

// ---------------- scores: planes in (q,k), W planes out + fused min/max ----------------
__global__ __launch_bounds__(256)
void mma_scores(int selfmask) {
    const int bh = blockIdx.z, b = bh >> 3, h = bh & 7;
    const int bs = blockIdx.x * 128, bt = blockIdx.y * 128;
    if (selfmask && bs > bt) return;
    extern __shared__ char dyn[];
    const uint32_t u0 = smem_u32(dyn);
    const int tid = threadIdx.x, wid = tid >> 5, lane = tid & 31;
    const int wm = (wid >> 2) * 64, wn = (wid & 3) * 32;
    const __nv_bfloat16* qh = g_qkvh + b * QKV_LD + h * HD;
    const __nv_bfloat16* ql = g_qkvl + b * QKV_LD + h * HD;
    const __nv_bfloat16* kh = g_qkvh + b * QKV_LD + EMBED + h * HD;
    const __nv_bfloat16* kl = g_qkvl + b * QKV_LD + EMBED + h * HD;
    const uint32_t PL = 128 * S64 * 2;  // plane stride bytes = 18432

#pragma unroll 1
    for (int i = tid; i < 1024; i += 256) {
        int r = i >> 3, c = (i & 7) * 8;
        uint32_t d = u0 + (r * S64 + c) * 2;
        size_t qo = (size_t)(bt + r) * ROWSTRIDE + c;
        size_t ko = (size_t)(bs + r) * ROWSTRIDE + c;
        cpa16(d,          qh + qo);
        cpa16(d + PL,     ql + qo);
        cpa16(d + 2 * PL, kh + ko);
        cpa16(d + 3 * PL, kl + ko);
    }
    CPA_COMMIT();
    CPA_WAIT0();
    __syncthreads();

    float acc[4][4][4] = {};
#pragma unroll
    for (int ks = 0; ks < 4; ks++) {
        uint32_t ah[4][4], al[4][4], bh[2][4], bl[2][4];
#pragma unroll
        for (int i = 0; i < 4; i++) {
            uint32_t off = u0 + ((wm + i * 16 + (lane & 15)) * S64 + ks * 16 + (lane >> 4) * 8) * 2;
            ldmx4(ah[i], off);
            ldmx4(al[i], off + PL);
        }
#pragma unroll
        for (int j2 = 0; j2 < 2; j2++) {
            uint32_t off = u0 + ((wn + j2 * 16 + ((lane >> 4) & 1) * 8 + (lane & 7)) * S64
                           + ks * 16 + ((lane >> 3) & 1) * 8) * 2;
            ldmx4(bh[j2], off + 2 * PL);
            ldmx4(bl[j2], off + 3 * PL);
        }
#pragma unroll
        for (int i = 0; i < 4; i++)
#pragma unroll
            for (int j = 0; j < 4; j++) {
                const uint32_t* bhf = &bh[j >> 1][(j & 1) * 2];
                const uint32_t* blf = &bl[j >> 1][(j & 1) * 2];
                mma16816(acc[i][j], ah[i], bhf);
                mma16816(acc[i][j], al[i], bhf);
                mma16816(acc[i][j], ah[i], blf);
            }
    }

    __nv_bfloat16* Whi = (__nv_bfloat16*)g_W;
    __nv_bfloat16* Wlo = Whi + BH * TT;
    float lmin = 3.4e38f, lmax = -3.4e38f;
#pragma unroll
    for (int i = 0; i < 4; i++) {
        const int t0 = bt + wm + i * 16 + (lane >> 2);
#pragma unroll
        for (int j = 0; j < 4; j++) {
            const int s = bs + wn + j * 8 + (lane & 3) * 2;
#pragma unroll
            for (int half = 0; half < 2; half++) {
                const int t = t0 + half * 8;
                float v0 = acc[i][j][half * 2 + 0] * 0.125f;
                float v1 = acc[i][j][half * 2 + 1] * 0.125f;
                if (selfmask) {
                    if (s + 0 > t) v0 = 0.f;
                    if (s + 1 > t) v1 = 0.f;
                }
                lmin = fminf(lmin, fminf(v0, v1));
                lmax = fmaxf(lmax, fmaxf(v0, v1));
                uint32_t hw, lw;
                cvt2(v0, v1, hw, lw);
                size_t off = (size_t)bh * TT + (size_t)t * T_SEQ + s;
                *(uint32_t*)(Whi + off) = hw;
                *(uint32_t*)(Wlo + off) = lw;
            }
        }
    }
#pragma unroll
    for (int off = 16; off > 0; off >>= 1) {
        lmin = fminf(lmin, __shfl_xor_sync(0xffffffffu, lmin, off));
        lmax = fmaxf(lmax, __shfl_xor_sync(0xffffffffu, lmax, off));
    }
    __shared__ float rmn[8], rmx[8];
    if (lane == 0) { rmn[wid] = lmin; rmx[wid] = lmax; }
    __syncthreads();
    if (tid == 0) {
        float mn = rmn[0], mx = rmx[0];
#pragma unroll
        for (int w = 1; w < 8; w++) { mn = fminf(mn, rmn[w]); mx = fmaxf(mx, rmx[w]); }
        atomicMin(&g_minmax[0], fenc(mn));
        atomicMax(&g_minmax[1], fenc(mx));
    }
}

// ---------------- AV: planes in (W, Vt), attn planes out ----------------
#define AV_STG 30720
__global__ __launch_bounds__(256)
void mma_av(int selfmask) {
    const int bh = blockIdx.z, b = bh >> 3, h = bh & 7;
    const int bm = blockIdx.y * 128;
    extern __shared__ char dyn[];
    const uint32_t u0 = smem_u32(dyn);
    const int tid = threadIdx.x, wid = tid >> 5, lane = tid & 31;
    const int wm = (wid >> 1) * 32, wn = (wid & 1) * 32;
    const __nv_bfloat16* Whi = (const __nv_bfloat16*)g_W;
    const __nv_bfloat16* Wlo = Whi + BH * TT;
    const __nv_bfloat16* Wh = Whi + (size_t)bh * TT + (size_t)bm * T_SEQ;
    const __nv_bfloat16* Wl = Wlo + (size_t)bh * TT + (size_t)bm * T_SEQ;
    const __nv_bfloat16* Vh = g_vth + (size_t)bh * 64 * 2048;
    const __nv_bfloat16* Vl = g_vtl + (size_t)bh * 64 * 2048;

    float acc[2][4][4] = {};
    const int nkt = selfmask ? (bm / 32 + 4) : 64;

#pragma unroll 1
    for (int i = tid; i < 512; i += 256) {
        int r = i >> 2, c = (i & 3) * 8;
        uint32_t d = u0 + (r * S32 + c) * 2;
        cpa16(d,         Wh + (size_t)r * T_SEQ + c);
        cpa16(d + 10240, Wl + (size_t)r * T_SEQ + c);
        if (i < 256) {
            cpa16(d + 20480, Vh + (size_t)r * 2048 + c);
            cpa16(d + 25600, Vl + (size_t)r * 2048 + c);
        }
    }
    CPA_COMMIT();

    for (int kt = 0; kt < nkt; kt++) {
        const uint32_t sb = u0 + (kt & 1) * AV_STG;
        if (kt + 1 < nkt) {
            const uint32_t nb = u0 + ((kt + 1) & 1) * AV_STG;
            const int kc = (kt + 1) * 32;
#pragma unroll 1
            for (int i = tid; i < 512; i += 256) {
                int r = i >> 2, c = (i & 3) * 8;
                uint32_t d = nb + (r * S32 + c) * 2;
                cpa16(d,         Wh + (size_t)r * T_SEQ + kc + c);
                cpa16(d + 10240, Wl + (size_t)r * T_SEQ + kc + c);
                if (i < 256) {
                    cpa16(d + 20480, Vh + (size_t)r * 2048 + kc + c);
                    cpa16(d + 25600, Vl + (size_t)r * 2048 + kc + c);
                }
            }
            CPA_COMMIT();
            CPA_WAIT1();
        } else {
            CPA_WAIT0();
        }
        __syncthreads();
#pragma unroll
        for (int ks = 0; ks < 2; ks++) {
            uint32_t ah[2][4], al[2][4], bh[2][4], bl[2][4];
#pragma unroll
            for (int i = 0; i < 2; i++) {
                uint32_t off = sb + ((wm + i * 16 + (lane & 15)) * S32 + ks * 16 + (lane >> 4) * 8) * 2;
                ldmx4(ah[i], off);
                ldmx4(al[i], off + 10240);
            }
#pragma unroll
            for (int j2 = 0; j2 < 2; j2++) {
                uint32_t off = sb + ((wn + j2 * 16 + ((lane >> 4) & 1) * 8 + (lane & 7)) * S32
                               + ks * 16 + ((lane >> 3) & 1) * 8) * 2;
                ldmx4(bh[j2], off + 20480);
                ldmx4(bl[j2], off + 25600);
            }
#pragma unroll
            for (int i = 0; i < 2; i++)
#pragma unroll
                for (int j = 0; j < 4; j++) {
                    const uint32_t* bhf = &bh[j >> 1][(j & 1) * 2];
                    const uint32_t* blf = &bl[j >> 1][(j & 1) * 2];
                    mma16816(acc[i][j], ah[i], bhf);
                    mma16816(acc[i][j], al[i], bhf);
                    mma16816(acc[i][j], ah[i], blf);
                }
        }
        __syncthreads();
    }

    const float mn = fdec(g_minmax[0]);
    const float mx = fdec(g_minmax[1]);
    const float inv = 1.f / (mx - mn);
#pragma unroll
    for (int i = 0; i < 2; i++) {
        const int t0 = bm + wm + i * 16 + (lane >> 2);
#pragma unroll
        for (int j = 0; j < 4; j++) {
            const int d = wn + j * 8 + (lane & 3) * 2;
            float vs0 = g_vsum[bh * 64 + d], vs1 = g_vsum[bh * 64 + d + 1];
#pragma unroll
            for (int half = 0; half < 2; half++) {
                const int t = t0 + half * 8;
                float v0 = (acc[i][j][half * 2 + 0] - mn * vs0) * inv;
                float v1 = (acc[i][j][half * 2 + 1] - mn * vs1) * inv;
                uint32_t hw, lw;
                cvt2(v0, v1, hw, lw);
                size_t off = (size_t)(t * BATCH + b) * EMBED + h * HD + d;
                *(uint32_t*)(g_ah + off) = hw;
                *(uint32_t*)(g_al + off) = lw;
            }
        }
    }
}

// ---------------- host orchestration ----------------
extern "C" void kernel_launch(void* const* d_in, const int* in_sizes, int n_in,
                              void* d_out, int out_size) {
    const float* x         = (const float*)d_in[0];
    const float* enc_out   = (const float*)d_in[1];
    const int*   tokens    = (const int*)d_in[2];
    const float* self_Wqkv = (const float*)d_in[3];
    const float* self_bqkv = (const float*)d_in[4];
    const float* self_Wo   = (const float*)d_in[5];
    const float* self_bo   = (const float*)d_in[6];
    const float* cross_Wqkv= (const float*)d_in[7];
    const float* cross_bqkv= (const float*)d_in[8];
    const float* cross_Wo  = (const float*)d_in[9];
    const float* cross_bo  = (const float*)d_in[10];
    const float* fc1_w     = (const float*)d_in[11];
    const float* fc1_b     = (const float*)d_in[12];
    const float* fc2_w     = (const float*)d_in[13];
    const float* fc2_b     = (const float*)d_in[14];
    const float* ln1_g     = (const float*)d_in[15];
    const float* ln1_b     = (const float*)d_in[16];
    const float* ln2_g     = (const float*)d_in[17];
    const float* ln2_b     = (const float*)d_in[18];
    const float* ln3_g     = (const float*)d_in[19];
    const float* ln3_b     = (const float*)d_in[20];

    float *px, *py;
    __nv_bfloat16 *pxh, *pxl, *pench, *pencl, *pqkvh, *pqkvl, *phidh, *phidl, *pah, *pal, *pwbh, *pwbl;
    cudaGetSymbolAddress((void**)&px, g_x);
    cudaGetSymbolAddress((void**)&py, g_y);
    cudaGetSymbolAddress((void**)&pxh, g_xh);
    cudaGetSymbolAddress((void**)&pxl, g_xl);
    cudaGetSymbolAddress((void**)&pench, g_ench);
    cudaGetSymbolAddress((void**)&pencl, g_encl);
    cudaGetSymbolAddress((void**)&pqkvh, g_qkvh);
    cudaGetSymbolAddress((void**)&pqkvl, g_qkvl);
    cudaGetSymbolAddress((void**)&phidh, g_hidh);
    cudaGetSymbolAddress((void**)&phidl, g_hidl);
    cudaGetSymbolAddress((void**)&pah, g_ah);
    cudaGetSymbolAddress((void**)&pal, g_al);
    cudaGetSymbolAddress((void**)&pwbh, g_wbh);
    cudaGetSymbolAddress((void**)&pwbl, g_wbl);

    const int SM_LIN = 2 * LIN_STG;        // 81920
    const int SM_SCO = 4 * 128 * S64 * 2;  // 73728
    const int SM_AV  = 2 * AV_STG;         // 61440
    cudaFuncSetAttribute(mma_linear, cudaFuncAttributeMaxDynamicSharedMemorySize, SM_LIN);
    cudaFuncSetAttribute(mma_scores, cudaFuncAttributeMaxDynamicSharedMemorySize, SM_SCO);
    cudaFuncSetAttribute(mma_av, cudaFuncAttributeMaxDynamicSharedMemorySize, SM_AV);

    // ---- one-time-per-launch conversions ----
    auto cvt = [&](const float* src, size_t off, int n) {
        cvt_planes<<<(n / 4 + 255) / 256, 256>>>(src, pwbh + off, pwbl + off, n / 4);
    };
    cvt(self_Wqkv, S_SQKV, 4 * QKV_LD * EMBED);
    cvt(self_Wo,   S_SWO,  4 * EMBED * EMBED);
    cvt(cross_Wqkv,S_CQKV, 4 * QKV_LD * EMBED);
    cvt(cross_Wo,  S_CWO,  4 * EMBED * EMBED);
    cvt(fc1_w,     S_FC1,  4 * FFN_DIM * EMBED);
    cvt(fc2_w,     S_FC2,  4 * EMBED * FFN_DIM);
    cvt_planes<<<(NROWS * EMBED / 4 + 255) / 256, 256>>>(enc_out, pench, pencl, NROWS * EMBED / 4);

    posembed_kernel<<<NROWS * EMBED / 4 / 256, 256>>>(x, tokens);

    const int BIG = 1 << 30;
    for (int l = 0; l < 4; l++) {
        // ---- self attention ----
        minmax_init_kernel<<<1, 1>>>(1);
        mma_linear<<<dim3(12, 32), 256, SM_LIN>>>(pxh, pxl, pxh, pxl, BIG,
            pwbh + S_SQKV + (size_t)l * QKV_LD * EMBED, pwbl + S_SQKV + (size_t)l * QKV_LD * EMBED,
            self_bqkv + l * QKV_LD, QKV_LD, EMBED, 1, nullptr, pqkvh, pqkvl);
        mma_scores<<<dim3(16, 16, 16), 256, SM_SCO>>>(1);
        vsum_kernel<<<16, 256>>>();
        vt_kernel<<<dim3(16, 16), 256>>>();
        mma_av<<<dim3(1, 16, 16), 256, SM_AV>>>(1);
        mma_linear<<<dim3(4, 32), 256, SM_LIN>>>(pah, pal, pah, pal, BIG,
            pwbh + S_SWO + (size_t)l * EMBED * EMBED, pwbl + S_SWO + (size_t)l * EMBED * EMBED,
            self_bo + l * EMBED, EMBED, EMBED, 0, py, nullptr, nullptr);
        ln_kernel<<<NROWS, 128>>>(px, py, ln1_g + l * EMBED, ln1_b + l * EMBED, px, pxh, pxl);

        // ---- cross attention ----
        minmax_init_kernel<<<1, 1>>>(0);
        mma_linear<<<dim3(12, 32), 256, SM_LIN>>>(pxh, pxl, pench, pencl, EMBED,
            pwbh + S_CQKV + (size_t)l * QKV_LD * EMBED, pwbl + S_CQKV + (size_t)l * QKV_LD * EMBED,
            cross_bqkv + l * QKV_LD, QKV_LD, EMBED, 1, nullptr, pqkvh, pqkvl);
        mma_scores<<<dim3(16, 16, 16), 256, SM_SCO>>>(0);
        vsum_kernel<<<16, 256>>>();
        vt_kernel<<<dim3(16, 16), 256>>>();
        mma_av<<<dim3(1, 16, 16), 256, SM_AV>>>(0);
        mma_linear<<<dim3(4, 32), 256, SM_LIN>>>(pah, pal, pah, pal, BIG,
            pwbh + S_CWO + (size_t)l * EMBED * EMBED, pwbl + S_CWO + (size_t)l * EMBED * EMBED,
            cross_bo + l * EMBED, EMBED, EMBED, 0, py, nullptr, nullptr);
        ln_kernel<<<NROWS, 128>>>(px, py, ln2_g + l * EMBED, ln2_b + l * EMBED, px, pxh, pxl);

        // ---- FFN ----
        mma_linear<<<dim3(16, 32), 256, SM_LIN>>>(pxh, pxl, pxh, pxl, BIG,
            pwbh + S_FC1 + (size_t)l * FFN_DIM * EMBED, pwbl + S_FC1 + (size_t)l * FFN_DIM * EMBED,
            fc1_b + l * FFN_DIM, FFN_DIM, EMBED, 2, nullptr, phidh, phidl);
        mma_linear<<<dim3(4, 32), 256, SM_LIN>>>(phidh, phidl, phidh, phidl, BIG,
            pwbh + S_FC2 + (size_t)l * EMBED * FFN_DIM, pwbl + S_FC2 + (size_t)l * EMBED * FFN_DIM,
            fc2_b + l * EMBED, EMBED, FFN_DIM, 0, py, nullptr, nullptr);
        float* lnout = (l == 3) ? (float*)d_out : px;
        ln_kernel<<<NROWS, 128>>>(px, py, ln3_g + l * EMBED, ln3_b + l * EMBED, lnout, pxh, pxl);
    }
}

// round 6
// speedup vs baseline: 2.6064x; 1.1267x over previous
#include <cuda_runtime.h>
#include <cuda_bf16.h>
#include <cstdint>

#define T_SEQ 2048
#define BATCH 2
#define EMBED 512
#define NHEADS 8
#define HD 64
#define FFN_DIM 2048
#define NROWS (T_SEQ * BATCH)      // 4096
#define BH (BATCH * NHEADS)        // 16
#define QKV_LD (3 * EMBED)         // 1536
#define ROWSTRIDE (BATCH * QKV_LD) // 3072
#define S32 40
#define SQ 72                      // stride for 64-col bf16 tiles (fused attn)
#define SV 136                     // stride for 128-col Vt tiles

// weight-plane segment offsets (elems)
#define S_SQKV 0
#define S_SWO  3145728
#define S_CQKV 4194304
#define S_CWO  7340032
#define S_FC1  8388608
#define S_FC2  12582912
#define W_TOT  16777216

// fused-attn smem layout
#define FA_QB 36864      // Q planes occupy [0, 36864)
#define FA_VOFF 36864    // Vt offset within a stage
#define FA_SSTG 71680    // stage stride (K planes 36864 + Vt planes 34816)
#define FA_SMEM (FA_QB + 2 * FA_SSTG)  // 180224

// ---------------- device scratch ----------------
__device__ __align__(16) float g_x[NROWS * EMBED];
__device__ __align__(16) float g_y[NROWS * EMBED];
__device__ __align__(16) __nv_bfloat16 g_xh[NROWS * EMBED], g_xl[NROWS * EMBED];
__device__ __align__(16) __nv_bfloat16 g_ench[NROWS * EMBED], g_encl[NROWS * EMBED];
__device__ __align__(16) __nv_bfloat16 g_qkvh[NROWS * QKV_LD], g_qkvl[NROWS * QKV_LD];
__device__ __align__(16) __nv_bfloat16 g_vth[BH * 64 * 2048], g_vtl[BH * 64 * 2048];
__device__ __align__(16) __nv_bfloat16 g_hidh[NROWS * FFN_DIM], g_hidl[NROWS * FFN_DIM];
__device__ __align__(16) __nv_bfloat16 g_ah[NROWS * EMBED], g_al[NROWS * EMBED];
__device__ __align__(16) __nv_bfloat16 g_wbh[W_TOT], g_wbl[W_TOT];
__device__ float g_vsum[BATCH * EMBED];   // [b][c] layout (== [bh][64])
__device__ float g_vs2[BATCH * EMBED];
__device__ unsigned g_minmax[2];

__device__ __forceinline__ unsigned fenc(float f) {
    unsigned u = __float_as_uint(f);
    return (u & 0x80000000u) ? ~u : (u | 0x80000000u);
}
__device__ __forceinline__ float fdec(unsigned e) {
    return __uint_as_float((e & 0x80000000u) ? (e ^ 0x80000000u) : ~e);
}
__device__ __forceinline__ uint32_t smem_u32(const void* p) {
    uint32_t a;
    asm("{ .reg .u64 t; cvta.to.shared.u64 t, %1; cvt.u32.u64 %0, t; }" : "=r"(a) : "l"(p));
    return a;
}
__device__ __forceinline__ void cpa16(uint32_t d, const void* s) {
    asm volatile("cp.async.cg.shared.global [%0], [%1], 16;" :: "r"(d), "l"(s));
}
#define CPA_COMMIT() asm volatile("cp.async.commit_group;" ::: "memory")
#define CPA_WAIT0()  asm volatile("cp.async.wait_group 0;" ::: "memory")
#define CPA_WAIT1()  asm volatile("cp.async.wait_group 1;" ::: "memory")

__device__ __forceinline__ void ldmx4(uint32_t* r, uint32_t addr) {
    asm volatile("ldmatrix.sync.aligned.m8n8.x4.shared.b16 {%0,%1,%2,%3}, [%4];"
        : "=r"(r[0]), "=r"(r[1]), "=r"(r[2]), "=r"(r[3]) : "r"(addr));
}
__device__ __forceinline__ void mma16816(float* c, const uint32_t* a, const uint32_t* b) {
    asm volatile("mma.sync.aligned.m16n8k16.row.col.f32.bf16.bf16.f32 "
        "{%0,%1,%2,%3}, {%4,%5,%6,%7}, {%8,%9}, {%0,%1,%2,%3};"
        : "+f"(c[0]), "+f"(c[1]), "+f"(c[2]), "+f"(c[3])
        : "r"(a[0]), "r"(a[1]), "r"(a[2]), "r"(a[3]), "r"(b[0]), "r"(b[1]));
}
__device__ __forceinline__ void cvt4(float4 v, uint2& uh, uint2& ul) {
    __nv_bfloat162 h01 = __floats2bfloat162_rn(v.x, v.y);
    __nv_bfloat162 h23 = __floats2bfloat162_rn(v.z, v.w);
    float2 f01 = __bfloat1622float2(h01);
    float2 f23 = __bfloat1622float2(h23);
    __nv_bfloat162 l01 = __floats2bfloat162_rn(v.x - f01.x, v.y - f01.y);
    __nv_bfloat162 l23 = __floats2bfloat162_rn(v.z - f23.x, v.w - f23.y);
    uh.x = *(uint32_t*)&h01; uh.y = *(uint32_t*)&h23;
    ul.x = *(uint32_t*)&l01; ul.y = *(uint32_t*)&l23;
}
__device__ __forceinline__ void cvt2(float v0, float v1, uint32_t& h, uint32_t& l) {
    __nv_bfloat162 hh = __floats2bfloat162_rn(v0, v1);
    float2 hf = __bfloat1622float2(hh);
    __nv_bfloat162 ll = __floats2bfloat162_rn(v0 - hf.x, v1 - hf.y);
    h = *(uint32_t*)&hh; l = *(uint32_t*)&ll;
}

// ---------------- small kernels ----------------
__global__ void minmax_init_kernel(int selfmask) {
    if (selfmask) { g_minmax[0] = fenc(0.f); g_minmax[1] = fenc(0.f); }
    else          { g_minmax[0] = 0xFFFFFFFFu; g_minmax[1] = 0u; }
}

__global__ void cvt_planes(const float* __restrict__ src,
                           __nv_bfloat16* __restrict__ dh,
                           __nv_bfloat16* __restrict__ dl, int n4) {
    int i = blockIdx.x * 256 + threadIdx.x;
    if (i >= n4) return;
    float4 v = ((const float4*)src)[i];
    uint2 uh, ul;
    cvt4(v, uh, ul);
    ((uint2*)dh)[i] = uh;
    ((uint2*)dl)[i] = ul;
}

__global__ void posembed_kernel(const float* __restrict__ x,
                                const int* __restrict__ tokens) {
    int i = blockIdx.x * 256 + threadIdx.x;
    int c4 = (i & 127) * 4;
    int row = i >> 7;
    int t = row >> 1, b = row & 1;
    int tok = tokens[b * T_SEQ + t];
    float4 v = ((const float4*)x)[i];
    if (tok != 0) {
        float p = (float)(t + 1);
        float* pv = (float*)&v;
#pragma unroll
        for (int e = 0; e < 4; e++) {
            int c = c4 + e;
            int ii = (c < 256) ? c : c - 256;
            float ang = p * expf((float)ii * (-9.210340371976184f / 255.0f));
            pv[e] += (c < 256) ? sinf(ang) : cosf(ang);
        }
    }
    ((float4*)g_x)[i] = v;
    uint2 uh, ul;
    cvt4(v, uh, ul);
    ((uint2*)g_xh)[i] = uh;
    ((uint2*)g_xl)[i] = ul;
}

__global__ void vsum_kernel() {
    const int bh = blockIdx.x;
    const int b = bh >> 3, h = bh & 7;
    const __nv_bfloat16* vh = g_qkvh + b * QKV_LD + 2 * EMBED + h * HD;
    const __nv_bfloat16* vl = g_qkvl + b * QKV_LD + 2 * EMBED + h * HD;
    const int d = threadIdx.x & 63;
    const int part = threadIdx.x >> 6;
    float s = 0.f;
    for (int i = part * 512; i < part * 512 + 512; i++) {
        size_t off = (size_t)i * ROWSTRIDE + d;
        s += __bfloat162float(vh[off]) + __bfloat162float(vl[off]);
    }
    __shared__ float sm[256];
    sm[threadIdx.x] = s;
    __syncthreads();
    if (threadIdx.x < 64)
        g_vsum[b * EMBED + h * HD + d] = sm[d] + sm[64 + d] + sm[128 + d] + sm[192 + d];
}

// vs2[b][n] = sum_c vsum[b][c] * Wo[n][c]
__global__ void vs2_kernel(const float* __restrict__ Wo) {
    int idx = blockIdx.x * 256 + threadIdx.x;  // 1024
    int b = idx >> 9, n = idx & 511;
    const float* vs = g_vsum + b * EMBED;
    const float* w = Wo + (size_t)n * EMBED;
    float s = 0.f;
    for (int c = 0; c < EMBED; c += 4) {
        float4 wv = *(const float4*)(w + c);
        s += vs[c] * wv.x + vs[c + 1] * wv.y + vs[c + 2] * wv.z + vs[c + 3] * wv.w;
    }
    g_vs2[idx] = s;
}

__global__ void ln_kernel(const float* __restrict__ res, const float* __restrict__ y,
                          const float* __restrict__ gam, const float* __restrict__ bet,
                          float* __restrict__ out,
                          __nv_bfloat16* __restrict__ outh, __nv_bfloat16* __restrict__ outl) {
    const int row = blockIdx.x;
    const int tid = threadIdx.x;
    const size_t base = (size_t)row * EMBED;
    float4 r4 = *(const float4*)(res + base + tid * 4);
    float4 y4 = *(const float4*)(y + base + tid * 4);
    float v0 = r4.x + y4.x, v1 = r4.y + y4.y, v2 = r4.z + y4.z, v3 = r4.w + y4.w;
    float s = v0 + v1 + v2 + v3;
    float q = v0 * v0 + v1 * v1 + v2 * v2 + v3 * v3;
#pragma unroll
    for (int off = 16; off > 0; off >>= 1) {
        s += __shfl_down_sync(0xffffffffu, s, off);
        q += __shfl_down_sync(0xffffffffu, q, off);
    }
    __shared__ float sm[8];
    __shared__ float stats[2];
    const int wid = tid >> 5, lane = tid & 31;
    if (lane == 0) { sm[wid] = s; sm[4 + wid] = q; }
    __syncthreads();
    if (tid == 0) {
        float S = sm[0] + sm[1] + sm[2] + sm[3];
        float Q = sm[4] + sm[5] + sm[6] + sm[7];
        float mu = S * (1.f / 512.f);
        float var = Q * (1.f / 512.f) - mu * mu;
        stats[0] = mu;
        stats[1] = rsqrtf(fmaxf(var, 0.f) + 1e-20f);
    }
    __syncthreads();
    const float mu = stats[0], rs = stats[1];
    const int c = tid * 4;
    float4 g4 = *(const float4*)(gam + c);
    float4 b4 = *(const float4*)(bet + c);
    float4 o;
    o.x = (v0 - mu) * rs * g4.x + b4.x;
    o.y = (v1 - mu) * rs * g4.y + b4.y;
    o.z = (v2 - mu) * rs * g4.z + b4.z;
    o.w = (v3 - mu) * rs * g4.w + b4.w;
    *(float4*)(out + base + c) = o;
    uint2 uh, ul;
    cvt4(o, uh, ul);
    *(uint2*)(outh + base + c) = uh;
    *(uint2*)(outl + base + c) = ul;
}

// ---------------- V transpose (bf16 planes -> Vt planes) ----------------
__global__ __launch_bounds__(256)
void vt_kernel() {
    __shared__ __nv_bfloat16 th[64][132], tl[64][132];
    const int bh = blockIdx.y, b = bh >> 3, h = bh & 7;
    const int s0 = blockIdx.x * 128;
    const __nv_bfloat16* vh = g_qkvh + b * QKV_LD + 2 * EMBED + h * HD;
    const __nv_bfloat16* vl = g_qkvl + b * QKV_LD + 2 * EMBED + h * HD;
    const int tid = threadIdx.x;
    for (int i = tid; i < 2048; i += 256) {
        int r = i >> 4, q = (i & 15) * 4;
        size_t off = (size_t)(s0 + r) * ROWSTRIDE + q;
        uint2 ah = *(const uint2*)(vh + off);
        uint2 al = *(const uint2*)(vl + off);
        __nv_bfloat16* ph = (__nv_bfloat16*)&ah;
        __nv_bfloat16* pl = (__nv_bfloat16*)&al;
#pragma unroll
        for (int e = 0; e < 4; e++) { th[q + e][r] = ph[e]; tl[q + e][r] = pl[e]; }
    }
    __syncthreads();
    for (int i = tid; i < 2048; i += 256) {
        int d = i >> 5, s4 = (i & 31) * 4;
        size_t off = (size_t)bh * 64 * 2048 + (size_t)d * 2048 + s0 + s4;
        *(uint2*)(g_vth + off) = *(uint2*)&th[d][s4];
        *(uint2*)(g_vtl + off) = *(uint2*)&tl[d][s4];
    }
}

// ---------------- fused attention: O_raw = mask(QK^T*scale) @ V, + global min/max ----
__global__ __launch_bounds__(256, 1)
void fused_attn(int selfmask) {
    const int bh = blockIdx.y, b = bh >> 3, h = bh & 7;
    const int bt = blockIdx.x * 128;
    extern __shared__ char dyn[];
    const uint32_t u0 = smem_u32(dyn);
    const int tid = threadIdx.x, wid = tid >> 5, lane = tid & 31;
    const int trow = wid * 16;
    const __nv_bfloat16* qh = g_qkvh + b * QKV_LD + h * HD;
    const __nv_bfloat16* ql = g_qkvl + b * QKV_LD + h * HD;
    const __nv_bfloat16* kh = g_qkvh + b * QKV_LD + EMBED + h * HD;
    const __nv_bfloat16* kl = g_qkvl + b * QKV_LD + EMBED + h * HD;
    const __nv_bfloat16* vth = g_vth + (size_t)bh * 64 * 2048;
    const __nv_bfloat16* vtl = g_vtl + (size_t)bh * 64 * 2048;
    const int nst = selfmask ? (bt / 128 + 1) : 16;

    // Q load + stage-0 K/Vt (one group)
#pragma unroll 1
    for (int i = tid; i < 1024; i += 256) {
        int r = i >> 3, c = (i & 7) * 8;
        uint32_t d = u0 + (r * SQ + c) * 2;
        cpa16(d,         qh + (size_t)(bt + r) * ROWSTRIDE + c);
        cpa16(d + 18432, ql + (size_t)(bt + r) * ROWSTRIDE + c);
        uint32_t dk = u0 + FA_QB + (r * SQ + c) * 2;
        cpa16(dk,         kh + (size_t)r * ROWSTRIDE + c);
        cpa16(dk + 18432, kl + (size_t)r * ROWSTRIDE + c);
    }
#pragma unroll 1
    for (int i = tid; i < 1024; i += 256) {
        int r = i >> 4, c = (i & 15) * 8;
        uint32_t d = u0 + FA_QB + FA_VOFF + (r * SV + c) * 2;
        cpa16(d,         vth + (size_t)r * 2048 + c);
        cpa16(d + 17408, vtl + (size_t)r * 2048 + c);
    }
    CPA_COMMIT();

    uint32_t qfh[4][4], qfl[4][4];
    float oacc[8][4] = {};
    float lmin = 3.4e38f, lmax = -3.4e38f;

    for (int st = 0; st < nst; st++) {
        const uint32_t sb = u0 + FA_QB + (st & 1) * FA_SSTG;
        if (st + 1 < nst) {
            const uint32_t nb = u0 + FA_QB + ((st + 1) & 1) * FA_SSTG;
            const int s0 = (st + 1) * 128;
#pragma unroll 1
            for (int i = tid; i < 1024; i += 256) {
                int r = i >> 3, c = (i & 7) * 8;
                uint32_t d = nb + (r * SQ + c) * 2;
                cpa16(d,         kh + (size_t)(s0 + r) * ROWSTRIDE + c);
                cpa16(d + 18432, kl + (size_t)(s0 + r) * ROWSTRIDE + c);
            }
#pragma unroll 1
            for (int i = tid; i < 1024; i += 256) {
                int r = i >> 4, c = (i & 15) * 8;
                uint32_t d = nb + FA_VOFF + (r * SV + c) * 2;
                cpa16(d,         vth + (size_t)r * 2048 + s0 + c);
                cpa16(d + 17408, vtl + (size_t)r * 2048 + s0 + c);
            }
            CPA_COMMIT();
            CPA_WAIT1();
        } else {
            CPA_WAIT0();
        }
        __syncthreads();
        if (st == 0) {
#pragma unroll
            for (int ks = 0; ks < 4; ks++) {
                uint32_t off = u0 + ((trow + (lane & 15)) * SQ + ks * 16 + (lane >> 4) * 8) * 2;
                ldmx4(qfh[ks], off);
                ldmx4(qfl[ks], off + 18432);
            }
        }
        // ---- S = Q @ K^T (warp slab: 16 t-rows x 128 s-cols) ----
        float sacc[16][4] = {};
#pragma unroll
        for (int ks = 0; ks < 4; ks++) {
#pragma unroll
            for (int j4 = 0; j4 < 8; j4++) {
                uint32_t off = sb + ((j4 * 16 + ((lane >> 4) & 1) * 8 + (lane & 7)) * SQ
                               + ks * 16 + ((lane >> 3) & 1) * 8) * 2;
                uint32_t kbh[4], kbl[4];
                ldmx4(kbh, off);
                ldmx4(kbl, off + 18432);
#pragma unroll
                for (int jj = 0; jj < 2; jj++) {
                    int j = j4 * 2 + jj;
                    mma16816(sacc[j], qfh[ks], &kbh[jj * 2]);
                    mma16816(sacc[j], qfl[ks], &kbh[jj * 2]);
                    mma16816(sacc[j], qfh[ks], &kbl[jj * 2]);
                }
            }
        }
        // ---- scale/mask/minmax + repack C-frags into A-frags (registers only) ----
        const int diag = selfmask && (st == nst - 1);
        const int tg0 = bt + trow + (lane >> 2);
        const int sg0 = st * 128 + (lane & 3) * 2;
        uint32_t sfh[8][4], sfl[8][4];
#pragma unroll
        for (int j = 0; j < 16; j++) {
            float v0 = sacc[j][0] * 0.125f, v1 = sacc[j][1] * 0.125f;
            float v2 = sacc[j][2] * 0.125f, v3 = sacc[j][3] * 0.125f;
            if (diag) {
                int s = sg0 + j * 8;
                if (s + 0 > tg0) v0 = 0.f;
                if (s + 1 > tg0) v1 = 0.f;
                if (s + 0 > tg0 + 8) v2 = 0.f;
                if (s + 1 > tg0 + 8) v3 = 0.f;
            }
            lmin = fminf(lmin, fminf(fminf(v0, v1), fminf(v2, v3)));
            lmax = fmaxf(lmax, fmaxf(fmaxf(v0, v1), fmaxf(v2, v3)));
            int p = j >> 1, q = (j & 1) * 2;
            cvt2(v0, v1, sfh[p][q], sfl[p][q]);
            cvt2(v2, v3, sfh[p][q + 1], sfl[p][q + 1]);
        }
        // ---- O += S @ V (B = Vt[d][s] col operand) ----
        const uint32_t vb = sb + FA_VOFF;
#pragma unroll
        for (int p = 0; p < 8; p++) {
#pragma unroll
            for (int jd4 = 0; jd4 < 4; jd4++) {
                uint32_t off = vb + ((jd4 * 16 + ((lane >> 4) & 1) * 8 + (lane & 7)) * SV
                               + p * 16 + ((lane >> 3) & 1) * 8) * 2;
                uint32_t vbh[4], vbl[4];
                ldmx4(vbh, off);
                ldmx4(vbl, off + 17408);
#pragma unroll
                for (int jj = 0; jj < 2; jj++) {
                    int jd = jd4 * 2 + jj;
                    mma16816(oacc[jd], sfh[p], &vbh[jj * 2]);
                    mma16816(oacc[jd], sfl[p], &vbh[jj * 2]);
                    mma16816(oacc[jd], sfh[p], &vbl[jj * 2]);
                }
            }
        }
        __syncthreads();
    }

    // ---- epilogue: write O_raw bf16 planes ----
    const int r = lane >> 2, tig = lane & 3;
#pragma unroll
    for (int jd = 0; jd < 8; jd++) {
        const int d = jd * 8 + tig * 2;
#pragma unroll
        for (int half = 0; half < 2; half++) {
            const int t = bt + trow + r + half * 8;
            uint32_t hw, lw;
            cvt2(oacc[jd][half * 2], oacc[jd][half * 2 + 1], hw, lw);
            size_t off = (size_t)(t * BATCH + b) * EMBED + h * HD + d;
            *(uint32_t*)(g_ah + off) = hw;
            *(uint32_t*)(g_al + off) = lw;
        }
    }
    // ---- global min/max ----
#pragma unroll
    for (int off = 16; off > 0; off >>= 1) {
        lmin = fminf(lmin, __shfl_xor_sync(0xffffffffu, lmin, off));
        lmax = fmaxf(lmax, __shfl_xor_sync(0xffffffffu, lmax, off));
    }
    __shared__ float rmn[8], rmx[8];
    if (lane == 0) { rmn[wid] = lmin; rmx[wid] = lmax; }
    __syncthreads();
    if (tid == 0) {
        float mn = rmn[0], mx = rmx[0];
#pragma unroll
        for (int w = 1; w < 8; w++) { mn = fminf(mn, rmn[w]); mx = fmaxf(mx, rmx[w]); }
        atomicMin(&g_minmax[0], fenc(mn));
        atomicMax(&g_minmax[1], fenc(mx));
    }
}

// ---------------- mma linear (bf16 planes in, cp.async 2-stage) ----------------
// mode 0: fp32 out; 1: bf16 planes out; 2: planes + relu; 3: fp32 out w/ deferred
// min-max normalization: out = (acc - mn*vs2[b][n])/(mx-mn) + bias
#define LIN_STG 40960
__global__ __launch_bounds__(256)
void mma_linear(const __nv_bfloat16* __restrict__ Aqh, const __nv_bfloat16* __restrict__ Aql,
                const __nv_bfloat16* __restrict__ Akvh, const __nv_bfloat16* __restrict__ Akvl,
                int nsplit,
                const __nv_bfloat16* __restrict__ Bh, const __nv_bfloat16* __restrict__ Bl,
                const float* __restrict__ bias, int N, int K, int mode,
                const float* __restrict__ vs2,
                float* __restrict__ Cf, __nv_bfloat16* __restrict__ Ch,
                __nv_bfloat16* __restrict__ Cl) {
    extern __shared__ char dyn[];
    const uint32_t u0 = smem_u32(dyn);
    const int tid = threadIdx.x, wid = tid >> 5, lane = tid & 31;
    const int bn = blockIdx.x * 128, bm = blockIdx.y * 128;
    const __nv_bfloat16* Ah = (bn < nsplit) ? Aqh : Akvh;
    const __nv_bfloat16* Al = (bn < nsplit) ? Aql : Akvl;
    const int wm = (wid >> 2) * 64, wn = (wid & 3) * 32;

    float acc[4][4][4] = {};
    const int nkt = K >> 5;

#pragma unroll 1
    for (int i = tid; i < 512; i += 256) {
        int r = i >> 2, c = (i & 3) * 8;
        uint32_t d = u0 + (r * S32 + c) * 2;
        cpa16(d,         Ah + (size_t)(bm + r) * K + c);
        cpa16(d + 10240, Al + (size_t)(bm + r) * K + c);
        cpa16(d + 20480, Bh + (size_t)(bn + r) * K + c);
        cpa16(d + 30720, Bl + (size_t)(bn + r) * K + c);
    }
    CPA_COMMIT();

    for (int kt = 0; kt < nkt; kt++) {
        const uint32_t sb = u0 + (kt & 1) * LIN_STG;
        if (kt + 1 < nkt) {
            const uint32_t nb = u0 + ((kt + 1) & 1) * LIN_STG;
            const int kc = (kt + 1) * 32;
#pragma unroll 1
            for (int i = tid; i < 512; i += 256) {
                int r = i >> 2, c = (i & 3) * 8;
                uint32_t d = nb + (r * S32 + c) * 2;
                cpa16(d,         Ah + (size_t)(bm + r) * K + kc + c);
                cpa16(d + 10240, Al + (size_t)(bm + r) * K + kc + c);
                cpa16(d + 20480, Bh + (size_t)(bn + r) * K + kc + c);
                cpa16(d + 30720, Bl + (size_t)(bn + r) * K + kc + c);
            }
            CPA_COMMIT();
            CPA_WAIT1();
        } else {
            CPA_WAIT0();
        }
        __syncthreads();
#pragma unroll
        for (int ks = 0; ks < 2; ks++) {
            uint32_t ah[4][4], al[4][4], bh[2][4], bl[2][4];
#pragma unroll
            for (int i = 0; i < 4; i++) {
                uint32_t off = sb + ((wm + i * 16 + (lane & 15)) * S32 + ks * 16 + (lane >> 4) * 8) * 2;
                ldmx4(ah[i], off);
                ldmx4(al[i], off + 10240);
            }
#pragma unroll
            for (int j2 = 0; j2 < 2; j2++) {
                uint32_t off = sb + ((wn + j2 * 16 + ((lane >> 4) & 1) * 8 + (lane & 7)) * S32
                               + ks * 16 + ((lane >> 3) & 1) * 8) * 2;
                ldmx4(bh[j2], off + 20480);
                ldmx4(bl[j2], off + 30720);
            }
#pragma unroll
            for (int i = 0; i < 4; i++)
#pragma unroll
                for (int j = 0; j < 4; j++) {
                    const uint32_t* bhf = &bh[j >> 1][(j & 1) * 2];
                    const uint32_t* blf = &bl[j >> 1][(j & 1) * 2];
                    mma16816(acc[i][j], ah[i], bhf);
                    mma16816(acc[i][j], al[i], bhf);
                    mma16816(acc[i][j], ah[i], blf);
                }
        }
        __syncthreads();
    }
    float mn = 0.f, inv = 1.f;
    if (mode == 3) {
        mn = fdec(g_minmax[0]);
        inv = 1.f / (fdec(g_minmax[1]) - mn);
    }
#pragma unroll
    for (int i = 0; i < 4; i++) {
        const int m0 = bm + wm + i * 16 + (lane >> 2);
#pragma unroll
        for (int j = 0; j < 4; j++) {
            const int n0 = bn + wn + j * 8 + (lane & 3) * 2;
            float b0 = bias[n0], b1 = bias[n0 + 1];
#pragma unroll
            for (int half = 0; half < 2; half++) {
                const int m = m0 + half * 8;
                float v0 = acc[i][j][half * 2 + 0];
                float v1 = acc[i][j][half * 2 + 1];
                if (mode == 3) {
                    const int bb = m & 1;
                    v0 = (v0 - mn * vs2[bb * EMBED + n0]) * inv + b0;
                    v1 = (v1 - mn * vs2[bb * EMBED + n0 + 1]) * inv + b1;
                    float2 o = make_float2(v0, v1);
                    *(float2*)(Cf + (size_t)m * N + n0) = o;
                } else {
                    v0 += b0; v1 += b1;
                    if (mode == 2) { v0 = fmaxf(v0, 0.f); v1 = fmaxf(v1, 0.f); }
                    if (mode == 0) {
                        float2 o = make_float2(v0, v1);
                        *(float2*)(Cf + (size_t)m * N + n0) = o;
                    } else {
                        uint32_t hh, ll;
                        cvt2(v0, v1, hh, ll);
                        *(uint32_t*)(Ch + (size_t)m * N + n0) = hh;
                        *(uint32_t*)(Cl + (size_t)m * N + n0) = ll;
                    }
                }
            }
        }
    }
}

// ---------------- host orchestration ----------------
extern "C" void kernel_launch(void* const* d_in, const int* in_sizes, int n_in,
                              void* d_out, int out_size) {
    const float* x         = (const float*)d_in[0];
    const float* enc_out   = (const float*)d_in[1];
    const int*   tokens    = (const int*)d_in[2];
    const float* self_Wqkv = (const float*)d_in[3];
    const float* self_bqkv = (const float*)d_in[4];
    const float* self_Wo   = (const float*)d_in[5];
    const float* self_bo   = (const float*)d_in[6];
    const float* cross_Wqkv= (const float*)d_in[7];
    const float* cross_bqkv= (const float*)d_in[8];
    const float* cross_Wo  = (const float*)d_in[9];
    const float* cross_bo  = (const float*)d_in[10];
    const float* fc1_w     = (const float*)d_in[11];
    const float* fc1_b     = (const float*)d_in[12];
    const float* fc2_w     = (const float*)d_in[13];
    const float* fc2_b     = (const float*)d_in[14];
    const float* ln1_g     = (const float*)d_in[15];
    const float* ln1_b     = (const float*)d_in[16];
    const float* ln2_g     = (const float*)d_in[17];
    const float* ln2_b     = (const float*)d_in[18];
    const float* ln3_g     = (const float*)d_in[19];
    const float* ln3_b     = (const float*)d_in[20];

    float *px, *py, *pvs2;
    __nv_bfloat16 *pxh, *pxl, *pench, *pencl, *pqkvh, *pqkvl, *phidh, *phidl, *pah, *pal, *pwbh, *pwbl;
    cudaGetSymbolAddress((void**)&px, g_x);
    cudaGetSymbolAddress((void**)&py, g_y);
    cudaGetSymbolAddress((void**)&pvs2, g_vs2);
    cudaGetSymbolAddress((void**)&pxh, g_xh);
    cudaGetSymbolAddress((void**)&pxl, g_xl);
    cudaGetSymbolAddress((void**)&pench, g_ench);
    cudaGetSymbolAddress((void**)&pencl, g_encl);
    cudaGetSymbolAddress((void**)&pqkvh, g_qkvh);
    cudaGetSymbolAddress((void**)&pqkvl, g_qkvl);
    cudaGetSymbolAddress((void**)&phidh, g_hidh);
    cudaGetSymbolAddress((void**)&phidl, g_hidl);
    cudaGetSymbolAddress((void**)&pah, g_ah);
    cudaGetSymbolAddress((void**)&pal, g_al);
    cudaGetSymbolAddress((void**)&pwbh, g_wbh);
    cudaGetSymbolAddress((void**)&pwbl, g_wbl);

    const int SM_LIN = 2 * LIN_STG;  // 81920
    cudaFuncSetAttribute(mma_linear, cudaFuncAttributeMaxDynamicSharedMemorySize, SM_LIN);
    cudaFuncSetAttribute(fused_attn, cudaFuncAttributeMaxDynamicSharedMemorySize, FA_SMEM);

    auto cvt = [&](const float* src, size_t off, int n) {
        cvt_planes<<<(n / 4 + 255) / 256, 256>>>(src, pwbh + off, pwbl + off, n / 4);
    };
    cvt(self_Wqkv, S_SQKV, 4 * QKV_LD * EMBED);
    cvt(self_Wo,   S_SWO,  4 * EMBED * EMBED);
    cvt(cross_Wqkv,S_CQKV, 4 * QKV_LD * EMBED);
    cvt(cross_Wo,  S_CWO,  4 * EMBED * EMBED);
    cvt(fc1_w,     S_FC1,  4 * FFN_DIM * EMBED);
    cvt(fc2_w,     S_FC2,  4 * EMBED * FFN_DIM);
    cvt_planes<<<(NROWS * EMBED / 4 + 255) / 256, 256>>>(enc_out, pench, pencl, NROWS * EMBED / 4);

    posembed_kernel<<<NROWS * EMBED / 4 / 256, 256>>>(x, tokens);

    const int BIG = 1 << 30;
    for (int l = 0; l < 4; l++) {
        // ---- self attention ----
        minmax_init_kernel<<<1, 1>>>(1);
        mma_linear<<<dim3(12, 32), 256, SM_LIN>>>(pxh, pxl, pxh, pxl, BIG,
            pwbh + S_SQKV + (size_t)l * QKV_LD * EMBED, pwbl + S_SQKV + (size_t)l * QKV_LD * EMBED,
            self_bqkv + l * QKV_LD, QKV_LD, EMBED, 1, nullptr, nullptr, pqkvh, pqkvl);
        vt_kernel<<<dim3(16, 16), 256>>>();
        vsum_kernel<<<16, 256>>>();
        fused_attn<<<dim3(16, 16), 256, FA_SMEM>>>(1);
        vs2_kernel<<<4, 256>>>(self_Wo + (size_t)l * EMBED * EMBED);
        mma_linear<<<dim3(4, 32), 256, SM_LIN>>>(pah, pal, pah, pal, BIG,
            pwbh + S_SWO + (size_t)l * EMBED * EMBED, pwbl + S_SWO + (size_t)l * EMBED * EMBED,
            self_bo + l * EMBED, EMBED, EMBED, 3, pvs2, py, nullptr, nullptr);
        ln_kernel<<<NROWS, 128>>>(px, py, ln1_g + l * EMBED, ln1_b + l * EMBED, px, pxh, pxl);

        // ---- cross attention ----
        minmax_init_kernel<<<1, 1>>>(0);
        mma_linear<<<dim3(12, 32), 256, SM_LIN>>>(pxh, pxl, pench, pencl, EMBED,
            pwbh + S_CQKV + (size_t)l * QKV_LD * EMBED, pwbl + S_CQKV + (size_t)l * QKV_LD * EMBED,
            cross_bqkv + l * QKV_LD, QKV_LD, EMBED, 1, nullptr, nullptr, pqkvh, pqkvl);
        vt_kernel<<<dim3(16, 16), 256>>>();
        vsum_kernel<<<16, 256>>>();
        fused_attn<<<dim3(16, 16), 256, FA_SMEM>>>(0);
        vs2_kernel<<<4, 256>>>(cross_Wo + (size_t)l * EMBED * EMBED);
        mma_linear<<<dim3(4, 32), 256, SM_LIN>>>(pah, pal, pah, pal, BIG,
            pwbh + S_CWO + (size_t)l * EMBED * EMBED, pwbl + S_CWO + (size_t)l * EMBED * EMBED,
            cross_bo + l * EMBED, EMBED, EMBED, 3, pvs2, py, nullptr, nullptr);
        ln_kernel<<<NROWS, 128>>>(px, py, ln2_g + l * EMBED, ln2_b + l * EMBED, px, pxh, pxl);

        // ---- FFN ----
        mma_linear<<<dim3(16, 32), 256, SM_LIN>>>(pxh, pxl, pxh, pxl, BIG,
            pwbh + S_FC1 + (size_t)l * FFN_DIM * EMBED, pwbl + S_FC1 + (size_t)l * FFN_DIM * EMBED,
            fc1_b + l * FFN_DIM, FFN_DIM, EMBED, 2, nullptr, nullptr, phidh, phidl);
        mma_linear<<<dim3(4, 32), 256, SM_LIN>>>(phidh, phidl, phidh, phidl, BIG,
            pwbh + S_FC2 + (size_t)l * EMBED * FFN_DIM, pwbl + S_FC2 + (size_t)l * EMBED * FFN_DIM,
            fc2_b + l * EMBED, EMBED, FFN_DIM, 0, nullptr, py, nullptr, nullptr);
        float* lnout = (l == 3) ? (float*)d_out : px;
        ln_kernel<<<NROWS, 128>>>(px, py, ln3_g + l * EMBED, ln3_b + l * EMBED, lnout, pxh, pxl);
    }
}

// round 7
// speedup vs baseline: 2.7930x; 1.0716x over previous
#include <cuda_runtime.h>
#include <cuda_bf16.h>
#include <cstdint>

#define T_SEQ 2048
#define BATCH 2
#define EMBED 512
#define NHEADS 8
#define HD 64
#define FFN_DIM 2048
#define NROWS (T_SEQ * BATCH)      // 4096
#define BH (BATCH * NHEADS)        // 16
#define QKV_LD (3 * EMBED)         // 1536
#define ROWSTRIDE (BATCH * QKV_LD) // 3072
#define S32 40
#define SQ 72                      // stride (elems) for 64-col bf16 tiles

// weight-plane segment offsets (elems)
#define S_SQKV 0
#define S_SWO  3145728
#define S_CQKV 4194304
#define S_CWO  7340032
#define S_FC1  8388608
#define S_FC2  12582912
#define W_TOT  16777216

// fused-attn smem layout: Q planes [0,36864); stages of K(2 planes)+V(2 planes)
#define FA_QB 36864
#define FA_VOFF 36864
#define FA_SSTG 73728
#define FA_SMEM (FA_QB + 2 * FA_SSTG)  // 184320

// ---------------- device scratch ----------------
__device__ __align__(16) float g_x[NROWS * EMBED];
__device__ __align__(16) float g_y[NROWS * EMBED];
__device__ __align__(16) __nv_bfloat16 g_xh[NROWS * EMBED], g_xl[NROWS * EMBED];
__device__ __align__(16) __nv_bfloat16 g_ench[NROWS * EMBED], g_encl[NROWS * EMBED];
__device__ __align__(16) __nv_bfloat16 g_qkvh[NROWS * QKV_LD], g_qkvl[NROWS * QKV_LD];
__device__ __align__(16) __nv_bfloat16 g_hidh[NROWS * FFN_DIM], g_hidl[NROWS * FFN_DIM];
__device__ __align__(16) __nv_bfloat16 g_ah[NROWS * EMBED], g_al[NROWS * EMBED];
__device__ __align__(16) __nv_bfloat16 g_wbh[W_TOT], g_wbl[W_TOT];
__device__ float g_vsum[BATCH * EMBED];
__device__ float g_vs2[BATCH * EMBED];
__device__ unsigned g_minmax[2];

__device__ __forceinline__ unsigned fenc(float f) {
    unsigned u = __float_as_uint(f);
    return (u & 0x80000000u) ? ~u : (u | 0x80000000u);
}
__device__ __forceinline__ float fdec(unsigned e) {
    return __uint_as_float((e & 0x80000000u) ? (e ^ 0x80000000u) : ~e);
}
__device__ __forceinline__ uint32_t smem_u32(const void* p) {
    uint32_t a;
    asm("{ .reg .u64 t; cvta.to.shared.u64 t, %1; cvt.u32.u64 %0, t; }" : "=r"(a) : "l"(p));
    return a;
}
__device__ __forceinline__ void cpa16(uint32_t d, const void* s) {
    asm volatile("cp.async.cg.shared.global [%0], [%1], 16;" :: "r"(d), "l"(s));
}
#define CPA_COMMIT() asm volatile("cp.async.commit_group;" ::: "memory")
#define CPA_WAIT0()  asm volatile("cp.async.wait_group 0;" ::: "memory")
#define CPA_WAIT1()  asm volatile("cp.async.wait_group 1;" ::: "memory")

__device__ __forceinline__ void ldmx4(uint32_t* r, uint32_t addr) {
    asm volatile("ldmatrix.sync.aligned.m8n8.x4.shared.b16 {%0,%1,%2,%3}, [%4];"
        : "=r"(r[0]), "=r"(r[1]), "=r"(r[2]), "=r"(r[3]) : "r"(addr));
}
__device__ __forceinline__ void ldmx4t(uint32_t* r, uint32_t addr) {
    asm volatile("ldmatrix.sync.aligned.m8n8.x4.trans.shared.b16 {%0,%1,%2,%3}, [%4];"
        : "=r"(r[0]), "=r"(r[1]), "=r"(r[2]), "=r"(r[3]) : "r"(addr));
}
__device__ __forceinline__ void mma16816(float* c, const uint32_t* a, const uint32_t* b) {
    asm volatile("mma.sync.aligned.m16n8k16.row.col.f32.bf16.bf16.f32 "
        "{%0,%1,%2,%3}, {%4,%5,%6,%7}, {%8,%9}, {%0,%1,%2,%3};"
        : "+f"(c[0]), "+f"(c[1]), "+f"(c[2]), "+f"(c[3])
        : "r"(a[0]), "r"(a[1]), "r"(a[2]), "r"(a[3]), "r"(b[0]), "r"(b[1]));
}
__device__ __forceinline__ void cvt4(float4 v, uint2& uh, uint2& ul) {
    __nv_bfloat162 h01 = __floats2bfloat162_rn(v.x, v.y);
    __nv_bfloat162 h23 = __floats2bfloat162_rn(v.z, v.w);
    float2 f01 = __bfloat1622float2(h01);
    float2 f23 = __bfloat1622float2(h23);
    __nv_bfloat162 l01 = __floats2bfloat162_rn(v.x - f01.x, v.y - f01.y);
    __nv_bfloat162 l23 = __floats2bfloat162_rn(v.z - f23.x, v.w - f23.y);
    uh.x = *(uint32_t*)&h01; uh.y = *(uint32_t*)&h23;
    ul.x = *(uint32_t*)&l01; ul.y = *(uint32_t*)&l23;
}
__device__ __forceinline__ void cvt2(float v0, float v1, uint32_t& h, uint32_t& l) {
    __nv_bfloat162 hh = __floats2bfloat162_rn(v0, v1);
    float2 hf = __bfloat1622float2(hh);
    __nv_bfloat162 ll = __floats2bfloat162_rn(v0 - hf.x, v1 - hf.y);
    h = *(uint32_t*)&hh; l = *(uint32_t*)&ll;
}

// ---------------- small kernels ----------------
__global__ void cvt_planes(const float* __restrict__ src,
                           __nv_bfloat16* __restrict__ dh,
                           __nv_bfloat16* __restrict__ dl, int n4) {
    int i = blockIdx.x * 256 + threadIdx.x;
    if (i >= n4) return;
    float4 v = ((const float4*)src)[i];
    uint2 uh, ul;
    cvt4(v, uh, ul);
    ((uint2*)dh)[i] = uh;
    ((uint2*)dl)[i] = ul;
}

__global__ void posembed_kernel(const float* __restrict__ x,
                                const int* __restrict__ tokens) {
    int i = blockIdx.x * 256 + threadIdx.x;
    int c4 = (i & 127) * 4;
    int row = i >> 7;
    int t = row >> 1, b = row & 1;
    int tok = tokens[b * T_SEQ + t];
    float4 v = ((const float4*)x)[i];
    if (tok != 0) {
        float p = (float)(t + 1);
        float* pv = (float*)&v;
#pragma unroll
        for (int e = 0; e < 4; e++) {
            int c = c4 + e;
            int ii = (c < 256) ? c : c - 256;
            float ang = p * expf((float)ii * (-9.210340371976184f / 255.0f));
            pv[e] += (c < 256) ? sinf(ang) : cosf(ang);
        }
    }
    ((float4*)g_x)[i] = v;
    uint2 uh, ul;
    cvt4(v, uh, ul);
    ((uint2*)g_xh)[i] = uh;
    ((uint2*)g_xl)[i] = ul;
}

// vsum + folded min/max init (stream order guarantees init lands before fused_attn)
__global__ void vsum_kernel(int selfmask) {
    const int bh = blockIdx.x;
    if (bh == 0 && threadIdx.x == 0) {
        if (selfmask) { g_minmax[0] = fenc(0.f); g_minmax[1] = fenc(0.f); }
        else          { g_minmax[0] = 0xFFFFFFFFu; g_minmax[1] = 0u; }
    }
    const int b = bh >> 3, h = bh & 7;
    const __nv_bfloat16* vh = g_qkvh + b * QKV_LD + 2 * EMBED + h * HD;
    const __nv_bfloat16* vl = g_qkvl + b * QKV_LD + 2 * EMBED + h * HD;
    const int d = threadIdx.x & 63;
    const int part = threadIdx.x >> 6;
    float s = 0.f;
    for (int i = part * 512; i < part * 512 + 512; i++) {
        size_t off = (size_t)i * ROWSTRIDE + d;
        s += __bfloat162float(vh[off]) + __bfloat162float(vl[off]);
    }
    __shared__ float sm[256];
    sm[threadIdx.x] = s;
    __syncthreads();
    if (threadIdx.x < 64)
        g_vsum[b * EMBED + h * HD + d] = sm[d] + sm[64 + d] + sm[128 + d] + sm[192 + d];
}

// vs2[b][n] = sum_c vsum[b][c] * Wo[n][c]
__global__ void vs2_kernel(const float* __restrict__ Wo) {
    int idx = blockIdx.x * 256 + threadIdx.x;  // 1024
    int b = idx >> 9, n = idx & 511;
    const float* vs = g_vsum + b * EMBED;
    const float* w = Wo + (size_t)n * EMBED;
    float s = 0.f;
    for (int c = 0; c < EMBED; c += 4) {
        float4 wv = *(const float4*)(w + c);
        s += vs[c] * wv.x + vs[c + 1] * wv.y + vs[c + 2] * wv.z + vs[c + 3] * wv.w;
    }
    g_vs2[idx] = s;
}

// warp-per-row LN: 8 rows/block, shfl-only reduction
__global__ __launch_bounds__(256)
void ln_kernel(const float* __restrict__ res, const float* __restrict__ y,
               const float* __restrict__ gam, const float* __restrict__ bet,
               float* __restrict__ out,
               __nv_bfloat16* __restrict__ outh, __nv_bfloat16* __restrict__ outl) {
    const int row = blockIdx.x * 8 + (threadIdx.x >> 5);
    const int lane = threadIdx.x & 31;
    const size_t base = (size_t)row * EMBED;
    float v[16];
    float s = 0.f, q = 0.f;
#pragma unroll
    for (int k = 0; k < 4; k++) {
        const int c = lane * 4 + k * 128;
        float4 a = *(const float4*)(res + base + c);
        float4 bb = *(const float4*)(y + base + c);
        float t0 = a.x + bb.x, t1 = a.y + bb.y, t2 = a.z + bb.z, t3 = a.w + bb.w;
        v[k * 4 + 0] = t0; v[k * 4 + 1] = t1; v[k * 4 + 2] = t2; v[k * 4 + 3] = t3;
        s += t0 + t1 + t2 + t3;
        q += t0 * t0 + t1 * t1 + t2 * t2 + t3 * t3;
    }
#pragma unroll
    for (int off = 16; off > 0; off >>= 1) {
        s += __shfl_xor_sync(0xffffffffu, s, off);
        q += __shfl_xor_sync(0xffffffffu, q, off);
    }
    const float mu = s * (1.f / 512.f);
    const float var = q * (1.f / 512.f) - mu * mu;
    const float rs = rsqrtf(fmaxf(var, 0.f) + 1e-20f);
#pragma unroll
    for (int k = 0; k < 4; k++) {
        const int c = lane * 4 + k * 128;
        float4 g4 = *(const float4*)(gam + c);
        float4 b4 = *(const float4*)(bet + c);
        float4 o;
        o.x = (v[k * 4 + 0] - mu) * rs * g4.x + b4.x;
        o.y = (v[k * 4 + 1] - mu) * rs * g4.y + b4.y;
        o.z = (v[k * 4 + 2] - mu) * rs * g4.z + b4.z;
        o.w = (v[k * 4 + 3] - mu) * rs * g4.w + b4.w;
        *(float4*)(out + base + c) = o;
        uint2 uh, ul;
        cvt4(o, uh, ul);
        *(uint2*)(outh + base + c) = uh;
        *(uint2*)(outl + base + c) = ul;
    }
}

// ---------------- fused attention: O_raw = mask(QK^T*scale) @ V, + global min/max ----
// 1D grid 256: bh = bid & 15; tile = bid >> 4; self-attn reverses tile order (LPT).
__global__ __launch_bounds__(256, 1)
void fused_attn(int selfmask) {
    const int bid = blockIdx.x;
    const int bh = bid & 15, b = bh >> 3, h = bh & 7;
    const int tile = bid >> 4;
    const int bt = (selfmask ? (15 - tile) : tile) * 128;
    extern __shared__ char dyn[];
    const uint32_t u0 = smem_u32(dyn);
    const int tid = threadIdx.x, wid = tid >> 5, lane = tid & 31;
    const int trow = wid * 16;
    const __nv_bfloat16* qh = g_qkvh + b * QKV_LD + h * HD;
    const __nv_bfloat16* ql = g_qkvl + b * QKV_LD + h * HD;
    const __nv_bfloat16* kh = g_qkvh + b * QKV_LD + EMBED + h * HD;
    const __nv_bfloat16* kl = g_qkvl + b * QKV_LD + EMBED + h * HD;
    const __nv_bfloat16* vh = g_qkvh + b * QKV_LD + 2 * EMBED + h * HD;
    const __nv_bfloat16* vl = g_qkvl + b * QKV_LD + 2 * EMBED + h * HD;
    const int nst = selfmask ? (bt / 128 + 1) : 16;

    // prologue: Q planes + stage-0 K/V planes (one group)
#pragma unroll 1
    for (int i = tid; i < 1024; i += 256) {
        int r = i >> 3, c = (i & 7) * 8;
        uint32_t dq = u0 + (r * SQ + c) * 2;
        cpa16(dq,         qh + (size_t)(bt + r) * ROWSTRIDE + c);
        cpa16(dq + 18432, ql + (size_t)(bt + r) * ROWSTRIDE + c);
        uint32_t dk = u0 + FA_QB + (r * SQ + c) * 2;
        cpa16(dk,         kh + (size_t)r * ROWSTRIDE + c);
        cpa16(dk + 18432, kl + (size_t)r * ROWSTRIDE + c);
        cpa16(dk + 36864, vh + (size_t)r * ROWSTRIDE + c);
        cpa16(dk + 55296, vl + (size_t)r * ROWSTRIDE + c);
    }
    CPA_COMMIT();

    uint32_t qfh[4][4], qfl[4][4];
    float oacc[8][4] = {};
    float lmin = 3.4e38f, lmax = -3.4e38f;

    for (int st = 0; st < nst; st++) {
        const uint32_t sb = u0 + FA_QB + (st & 1) * FA_SSTG;
        if (st + 1 < nst) {
            const uint32_t nb = u0 + FA_QB + ((st + 1) & 1) * FA_SSTG;
            const int s0 = (st + 1) * 128;
#pragma unroll 1
            for (int i = tid; i < 1024; i += 256) {
                int r = i >> 3, c = (i & 7) * 8;
                uint32_t dk = nb + (r * SQ + c) * 2;
                cpa16(dk,         kh + (size_t)(s0 + r) * ROWSTRIDE + c);
                cpa16(dk + 18432, kl + (size_t)(s0 + r) * ROWSTRIDE + c);
                cpa16(dk + 36864, vh + (size_t)(s0 + r) * ROWSTRIDE + c);
                cpa16(dk + 55296, vl + (size_t)(s0 + r) * ROWSTRIDE + c);
            }
            CPA_COMMIT();
            CPA_WAIT1();
        } else {
            CPA_WAIT0();
        }
        __syncthreads();
        if (st == 0) {
#pragma unroll
            for (int ks = 0; ks < 4; ks++) {
                uint32_t off = u0 + ((trow + (lane & 15)) * SQ + ks * 16 + (lane >> 4) * 8) * 2;
                ldmx4(qfh[ks], off);
                ldmx4(qfl[ks], off + 18432);
            }
        }
        // ---- S = Q @ K^T ----
        float sacc[16][4] = {};
#pragma unroll
        for (int ks = 0; ks < 4; ks++) {
#pragma unroll
            for (int j4 = 0; j4 < 8; j4++) {
                uint32_t off = sb + ((j4 * 16 + ((lane >> 4) & 1) * 8 + (lane & 7)) * SQ
                               + ks * 16 + ((lane >> 3) & 1) * 8) * 2;
                uint32_t kbh[4], kbl[4];
                ldmx4(kbh, off);
                ldmx4(kbl, off + 18432);
#pragma unroll
                for (int jj = 0; jj < 2; jj++) {
                    int j = j4 * 2 + jj;
                    mma16816(sacc[j], qfh[ks], &kbh[jj * 2]);
                    mma16816(sacc[j], qfl[ks], &kbh[jj * 2]);
                    mma16816(sacc[j], qfh[ks], &kbl[jj * 2]);
                }
            }
        }
        // ---- scale/mask/minmax + register repack C-frag -> A-frag ----
        const int diag = selfmask && (st == nst - 1);
        const int tg0 = bt + trow + (lane >> 2);
        const int sg0 = st * 128 + (lane & 3) * 2;
        uint32_t sfh[8][4], sfl[8][4];
#pragma unroll
        for (int j = 0; j < 16; j++) {
            float v0 = sacc[j][0] * 0.125f, v1 = sacc[j][1] * 0.125f;
            float v2 = sacc[j][2] * 0.125f, v3 = sacc[j][3] * 0.125f;
            if (diag) {
                int s = sg0 + j * 8;
                if (s + 0 > tg0) v0 = 0.f;
                if (s + 1 > tg0) v1 = 0.f;
                if (s + 0 > tg0 + 8) v2 = 0.f;
                if (s + 1 > tg0 + 8) v3 = 0.f;
            }
            lmin = fminf(lmin, fminf(fminf(v0, v1), fminf(v2, v3)));
            lmax = fmaxf(lmax, fmaxf(fmaxf(v0, v1), fmaxf(v2, v3)));
            int p = j >> 1, q = (j & 1) * 2;
            cvt2(v0, v1, sfh[p][q], sfl[p][q]);
            cvt2(v2, v3, sfh[p][q + 1], sfl[p][q + 1]);
        }
        // ---- O += S @ V (B-frag via ldmatrix.trans on V[s][d]) ----
        const uint32_t vb = sb + FA_VOFF;
#pragma unroll
        for (int p = 0; p < 8; p++) {
#pragma unroll
            for (int jd4 = 0; jd4 < 4; jd4++) {
                uint32_t off = vb + ((p * 16 + (lane & 15)) * SQ + jd4 * 16 + (lane >> 4) * 8) * 2;
                uint32_t vbh[4], vbl[4];
                ldmx4t(vbh, off);
                ldmx4t(vbl, off + 18432);
#pragma unroll
                for (int jj = 0; jj < 2; jj++) {
                    int jd = jd4 * 2 + jj;
                    mma16816(oacc[jd], sfh[p], &vbh[jj * 2]);
                    mma16816(oacc[jd], sfl[p], &vbh[jj * 2]);
                    mma16816(oacc[jd], sfh[p], &vbl[jj * 2]);
                }
            }
        }
        __syncthreads();
    }

    // ---- epilogue: write O_raw bf16 planes ----
    const int r = lane >> 2, tig = lane & 3;
#pragma unroll
    for (int jd = 0; jd < 8; jd++) {
        const int d = jd * 8 + tig * 2;
#pragma unroll
        for (int half = 0; half < 2; half++) {
            const int t = bt + trow + r + half * 8;
            uint32_t hw, lw;
            cvt2(oacc[jd][half * 2], oacc[jd][half * 2 + 1], hw, lw);
            size_t off = (size_t)(t * BATCH + b) * EMBED + h * HD + d;
            *(uint32_t*)(g_ah + off) = hw;
            *(uint32_t*)(g_al + off) = lw;
        }
    }
    // ---- global min/max ----
#pragma unroll
    for (int off = 16; off > 0; off >>= 1) {
        lmin = fminf(lmin, __shfl_xor_sync(0xffffffffu, lmin, off));
        lmax = fmaxf(lmax, __shfl_xor_sync(0xffffffffu, lmax, off));
    }
    __shared__ float rmn[8], rmx[8];
    if (lane == 0) { rmn[wid] = lmin; rmx[wid] = lmax; }
    __syncthreads();
    if (tid == 0) {
        float mn = rmn[0], mx = rmx[0];
#pragma unroll
        for (int w = 1; w < 8; w++) { mn = fminf(mn, rmn[w]); mx = fmaxf(mx, rmx[w]); }
        atomicMin(&g_minmax[0], fenc(mn));
        atomicMax(&g_minmax[1], fenc(mx));
    }
}

// ---------------- mma linear (bf16 planes in, cp.async 2-stage) ----------------
// mode 0: fp32 out; 1: bf16 planes out; 2: planes + relu; 3: fp32 out w/ deferred
// min-max normalization: out = (acc - mn*vs2[b][n])/(mx-mn) + bias
#define LIN_STG 40960
__global__ __launch_bounds__(256)
void mma_linear(const __nv_bfloat16* __restrict__ Aqh, const __nv_bfloat16* __restrict__ Aql,
                const __nv_bfloat16* __restrict__ Akvh, const __nv_bfloat16* __restrict__ Akvl,
                int nsplit,
                const __nv_bfloat16* __restrict__ Bh, const __nv_bfloat16* __restrict__ Bl,
                const float* __restrict__ bias, int N, int K, int mode,
                const float* __restrict__ vs2,
                float* __restrict__ Cf, __nv_bfloat16* __restrict__ Ch,
                __nv_bfloat16* __restrict__ Cl) {
    extern __shared__ char dyn[];
    const uint32_t u0 = smem_u32(dyn);
    const int tid = threadIdx.x, wid = tid >> 5, lane = tid & 31;
    const int bn = blockIdx.x * 128, bm = blockIdx.y * 128;
    const __nv_bfloat16* Ah = (bn < nsplit) ? Aqh : Akvh;
    const __nv_bfloat16* Al = (bn < nsplit) ? Aql : Akvl;
    const int wm = (wid >> 2) * 64, wn = (wid & 3) * 32;

    float acc[4][4][4] = {};
    const int nkt = K >> 5;

#pragma unroll 1
    for (int i = tid; i < 512; i += 256) {
        int r = i >> 2, c = (i & 3) * 8;
        uint32_t d = u0 + (r * S32 + c) * 2;
        cpa16(d,         Ah + (size_t)(bm + r) * K + c);
        cpa16(d + 10240, Al + (size_t)(bm + r) * K + c);
        cpa16(d + 20480, Bh + (size_t)(bn + r) * K + c);
        cpa16(d + 30720, Bl + (size_t)(bn + r) * K + c);
    }
    CPA_COMMIT();

    for (int kt = 0; kt < nkt; kt++) {
        const uint32_t sb = u0 + (kt & 1) * LIN_STG;
        if (kt + 1 < nkt) {
            const uint32_t nb = u0 + ((kt + 1) & 1) * LIN_STG;
            const int kc = (kt + 1) * 32;
#pragma unroll 1
            for (int i = tid; i < 512; i += 256) {
                int r = i >> 2, c = (i & 3) * 8;
                uint32_t d = nb + (r * S32 + c) * 2;
                cpa16(d,         Ah + (size_t)(bm + r) * K + kc + c);
                cpa16(d + 10240, Al + (size_t)(bm + r) * K + kc + c);
                cpa16(d + 20480, Bh + (size_t)(bn + r) * K + kc + c);
                cpa16(d + 30720, Bl + (size_t)(bn + r) * K + kc + c);
            }
            CPA_COMMIT();
            CPA_WAIT1();
        } else {
            CPA_WAIT0();
        }
        __syncthreads();
#pragma unroll
        for (int ks = 0; ks < 2; ks++) {
            uint32_t ah[4][4], al[4][4], bh[2][4], bl[2][4];
#pragma unroll
            for (int i = 0; i < 4; i++) {
                uint32_t off = sb + ((wm + i * 16 + (lane & 15)) * S32 + ks * 16 + (lane >> 4) * 8) * 2;
                ldmx4(ah[i], off);
                ldmx4(al[i], off + 10240);
            }
#pragma unroll
            for (int j2 = 0; j2 < 2; j2++) {
                uint32_t off = sb + ((wn + j2 * 16 + ((lane >> 4) & 1) * 8 + (lane & 7)) * S32
                               + ks * 16 + ((lane >> 3) & 1) * 8) * 2;
                ldmx4(bh[j2], off + 20480);
                ldmx4(bl[j2], off + 30720);
            }
#pragma unroll
            for (int i = 0; i < 4; i++)
#pragma unroll
                for (int j = 0; j < 4; j++) {
                    const uint32_t* bhf = &bh[j >> 1][(j & 1) * 2];
                    const uint32_t* blf = &bl[j >> 1][(j & 1) * 2];
                    mma16816(acc[i][j], ah[i], bhf);
                    mma16816(acc[i][j], al[i], bhf);
                    mma16816(acc[i][j], ah[i], blf);
                }
        }
        __syncthreads();
    }
    float mn = 0.f, inv = 1.f;
    if (mode == 3) {
        mn = fdec(g_minmax[0]);
        inv = 1.f / (fdec(g_minmax[1]) - mn);
    }
#pragma unroll
    for (int i = 0; i < 4; i++) {
        const int m0 = bm + wm + i * 16 + (lane >> 2);
#pragma unroll
        for (int j = 0; j < 4; j++) {
            const int n0 = bn + wn + j * 8 + (lane & 3) * 2;
            float b0 = bias[n0], b1 = bias[n0 + 1];
#pragma unroll
            for (int half = 0; half < 2; half++) {
                const int m = m0 + half * 8;
                float v0 = acc[i][j][half * 2 + 0];
                float v1 = acc[i][j][half * 2 + 1];
                if (mode == 3) {
                    const int bb = m & 1;
                    v0 = (v0 - mn * vs2[bb * EMBED + n0]) * inv + b0;
                    v1 = (v1 - mn * vs2[bb * EMBED + n0 + 1]) * inv + b1;
                    float2 o = make_float2(v0, v1);
                    *(float2*)(Cf + (size_t)m * N + n0) = o;
                } else {
                    v0 += b0; v1 += b1;
                    if (mode == 2) { v0 = fmaxf(v0, 0.f); v1 = fmaxf(v1, 0.f); }
                    if (mode == 0) {
                        float2 o = make_float2(v0, v1);
                        *(float2*)(Cf + (size_t)m * N + n0) = o;
                    } else {
                        uint32_t hh, ll;
                        cvt2(v0, v1, hh, ll);
                        *(uint32_t*)(Ch + (size_t)m * N + n0) = hh;
                        *(uint32_t*)(Cl + (size_t)m * N + n0) = ll;
                    }
                }
            }
        }
    }
}

// ---------------- host orchestration ----------------
extern "C" void kernel_launch(void* const* d_in, const int* in_sizes, int n_in,
                              void* d_out, int out_size) {
    const float* x         = (const float*)d_in[0];
    const float* enc_out   = (const float*)d_in[1];
    const int*   tokens    = (const int*)d_in[2];
    const float* self_Wqkv = (const float*)d_in[3];
    const float* self_bqkv = (const float*)d_in[4];
    const float* self_Wo   = (const float*)d_in[5];
    const float* self_bo   = (const float*)d_in[6];
    const float* cross_Wqkv= (const float*)d_in[7];
    const float* cross_bqkv= (const float*)d_in[8];
    const float* cross_Wo  = (const float*)d_in[9];
    const float* cross_bo  = (const float*)d_in[10];
    const float* fc1_w     = (const float*)d_in[11];
    const float* fc1_b     = (const float*)d_in[12];
    const float* fc2_w     = (const float*)d_in[13];
    const float* fc2_b     = (const float*)d_in[14];
    const float* ln1_g     = (const float*)d_in[15];
    const float* ln1_b     = (const float*)d_in[16];
    const float* ln2_g     = (const float*)d_in[17];
    const float* ln2_b     = (const float*)d_in[18];
    const float* ln3_g     = (const float*)d_in[19];
    const float* ln3_b     = (const float*)d_in[20];

    float *px, *py, *pvs2;
    __nv_bfloat16 *pxh, *pxl, *pench, *pencl, *pqkvh, *pqkvl, *phidh, *phidl, *pah, *pal, *pwbh, *pwbl;
    cudaGetSymbolAddress((void**)&px, g_x);
    cudaGetSymbolAddress((void**)&py, g_y);
    cudaGetSymbolAddress((void**)&pvs2, g_vs2);
    cudaGetSymbolAddress((void**)&pxh, g_xh);
    cudaGetSymbolAddress((void**)&pxl, g_xl);
    cudaGetSymbolAddress((void**)&pench, g_ench);
    cudaGetSymbolAddress((void**)&pencl, g_encl);
    cudaGetSymbolAddress((void**)&pqkvh, g_qkvh);
    cudaGetSymbolAddress((void**)&pqkvl, g_qkvl);
    cudaGetSymbolAddress((void**)&phidh, g_hidh);
    cudaGetSymbolAddress((void**)&phidl, g_hidl);
    cudaGetSymbolAddress((void**)&pah, g_ah);
    cudaGetSymbolAddress((void**)&pal, g_al);
    cudaGetSymbolAddress((void**)&pwbh, g_wbh);
    cudaGetSymbolAddress((void**)&pwbl, g_wbl);

    const int SM_LIN = 2 * LIN_STG;  // 81920
    cudaFuncSetAttribute(mma_linear, cudaFuncAttributeMaxDynamicSharedMemorySize, SM_LIN);
    cudaFuncSetAttribute(fused_attn, cudaFuncAttributeMaxDynamicSharedMemorySize, FA_SMEM);

    auto cvt = [&](const float* src, size_t off, int n) {
        cvt_planes<<<(n / 4 + 255) / 256, 256>>>(src, pwbh + off, pwbl + off, n / 4);
    };
    cvt(self_Wqkv, S_SQKV, 4 * QKV_LD * EMBED);
    cvt(self_Wo,   S_SWO,  4 * EMBED * EMBED);
    cvt(cross_Wqkv,S_CQKV, 4 * QKV_LD * EMBED);
    cvt(cross_Wo,  S_CWO,  4 * EMBED * EMBED);
    cvt(fc1_w,     S_FC1,  4 * FFN_DIM * EMBED);
    cvt(fc2_w,     S_FC2,  4 * EMBED * FFN_DIM);
    cvt_planes<<<(NROWS * EMBED / 4 + 255) / 256, 256>>>(enc_out, pench, pencl, NROWS * EMBED / 4);

    posembed_kernel<<<NROWS * EMBED / 4 / 256, 256>>>(x, tokens);

    const int BIG = 1 << 30;
    for (int l = 0; l < 4; l++) {
        // ---- self attention ----
        mma_linear<<<dim3(12, 32), 256, SM_LIN>>>(pxh, pxl, pxh, pxl, BIG,
            pwbh + S_SQKV + (size_t)l * QKV_LD * EMBED, pwbl + S_SQKV + (size_t)l * QKV_LD * EMBED,
            self_bqkv + l * QKV_LD, QKV_LD, EMBED, 1, nullptr, nullptr, pqkvh, pqkvl);
        vsum_kernel<<<16, 256>>>(1);
        fused_attn<<<256, 256, FA_SMEM>>>(1);
        vs2_kernel<<<4, 256>>>(self_Wo + (size_t)l * EMBED * EMBED);
        mma_linear<<<dim3(4, 32), 256, SM_LIN>>>(pah, pal, pah, pal, BIG,
            pwbh + S_SWO + (size_t)l * EMBED * EMBED, pwbl + S_SWO + (size_t)l * EMBED * EMBED,
            self_bo + l * EMBED, EMBED, EMBED, 3, pvs2, py, nullptr, nullptr);
        ln_kernel<<<NROWS / 8, 256>>>(px, py, ln1_g + l * EMBED, ln1_b + l * EMBED, px, pxh, pxl);

        // ---- cross attention ----
        mma_linear<<<dim3(12, 32), 256, SM_LIN>>>(pxh, pxl, pench, pencl, EMBED,
            pwbh + S_CQKV + (size_t)l * QKV_LD * EMBED, pwbl + S_CQKV + (size_t)l * QKV_LD * EMBED,
            cross_bqkv + l * QKV_LD, QKV_LD, EMBED, 1, nullptr, nullptr, pqkvh, pqkvl);
        vsum_kernel<<<16, 256>>>(0);
        fused_attn<<<256, 256, FA_SMEM>>>(0);
        vs2_kernel<<<4, 256>>>(cross_Wo + (size_t)l * EMBED * EMBED);
        mma_linear<<<dim3(4, 32), 256, SM_LIN>>>(pah, pal, pah, pal, BIG,
            pwbh + S_CWO + (size_t)l * EMBED * EMBED, pwbl + S_CWO + (size_t)l * EMBED * EMBED,
            cross_bo + l * EMBED, EMBED, EMBED, 3, pvs2, py, nullptr, nullptr);
        ln_kernel<<<NROWS / 8, 256>>>(px, py, ln2_g + l * EMBED, ln2_b + l * EMBED, px, pxh, pxl);

        // ---- FFN ----
        mma_linear<<<dim3(16, 32), 256, SM_LIN>>>(pxh, pxl, pxh, pxl, BIG,
            pwbh + S_FC1 + (size_t)l * FFN_DIM * EMBED, pwbl + S_FC1 + (size_t)l * FFN_DIM * EMBED,
            fc1_b + l * FFN_DIM, FFN_DIM, EMBED, 2, nullptr, nullptr, phidh, phidl);
        mma_linear<<<dim3(4, 32), 256, SM_LIN>>>(phidh, phidl, phidh, phidl, BIG,
            pwbh + S_FC2 + (size_t)l * EMBED * FFN_DIM, pwbl + S_FC2 + (size_t)l * EMBED * FFN_DIM,
            fc2_b + l * EMBED, EMBED, FFN_DIM, 0, nullptr, py, nullptr, nullptr);
        float* lnout = (l == 3) ? (float*)d_out : px;
        ln_kernel<<<NROWS / 8, 256>>>(px, py, ln3_g + l * EMBED, ln3_b + l * EMBED, lnout, pxh, pxl);
    }
}

// round 8
// speedup vs baseline: 3.6408x; 1.3036x over previous
#include <cuda_runtime.h>
#include <cuda_fp16.h>
#include <cstdint>

#define T_SEQ 2048
#define BATCH 2
#define EMBED 512
#define NHEADS 8
#define HD 64
#define FFN_DIM 2048
#define NROWS (T_SEQ * BATCH)      // 4096
#define BH (BATCH * NHEADS)        // 16
#define QKV_LD (3 * EMBED)         // 1536
#define ROWSTRIDE (BATCH * QKV_LD) // 3072
#define S32 40
#define SQ 72                      // stride (elems) for 64-col fp16 tiles

// weight-plane segment offsets (elems) -- hi plane only
#define S_SQKV 0
#define S_SWO  3145728
#define S_CQKV 4194304
#define S_CWO  7340032
#define S_FC1  8388608
#define S_FC2  12582912
#define W_TOT  16777216

// fused-attn smem: Q hi/lo [0,36864); stages of K-hi + V-hi (36864 each)
#define FA_QB 36864
#define FA_VOFF 18432
#define FA_SSTG 36864
#define FA_SMEM (FA_QB + 2 * FA_SSTG)  // 110592

// ---------------- device scratch ----------------
__device__ __align__(16) float g_x[NROWS * EMBED];
__device__ __align__(16) float g_y[NROWS * EMBED];
__device__ __align__(16) __half g_xh[NROWS * EMBED], g_xl[NROWS * EMBED];
__device__ __align__(16) __half g_ench[NROWS * EMBED], g_encl[NROWS * EMBED];
__device__ __align__(16) __half g_qkvh[NROWS * QKV_LD], g_qkvl[NROWS * QKV_LD];
__device__ __align__(16) __half g_hidh[NROWS * FFN_DIM], g_hidl[NROWS * FFN_DIM];
__device__ __align__(16) __half g_ah[NROWS * EMBED], g_al[NROWS * EMBED];
__device__ __align__(16) __half g_wbh[W_TOT];
__device__ float g_vsum[BATCH * EMBED];
__device__ float g_vs2[BATCH * EMBED];
__device__ unsigned g_minmax[2];

__device__ __forceinline__ unsigned fenc(float f) {
    unsigned u = __float_as_uint(f);
    return (u & 0x80000000u) ? ~u : (u | 0x80000000u);
}
__device__ __forceinline__ float fdec(unsigned e) {
    return __uint_as_float((e & 0x80000000u) ? (e ^ 0x80000000u) : ~e);
}
__device__ __forceinline__ uint32_t smem_u32(const void* p) {
    uint32_t a;
    asm("{ .reg .u64 t; cvta.to.shared.u64 t, %1; cvt.u32.u64 %0, t; }" : "=r"(a) : "l"(p));
    return a;
}
__device__ __forceinline__ void cpa16(uint32_t d, const void* s) {
    asm volatile("cp.async.cg.shared.global [%0], [%1], 16;" :: "r"(d), "l"(s));
}
#define CPA_COMMIT() asm volatile("cp.async.commit_group;" ::: "memory")
#define CPA_WAIT0()  asm volatile("cp.async.wait_group 0;" ::: "memory")
#define CPA_WAIT1()  asm volatile("cp.async.wait_group 1;" ::: "memory")

__device__ __forceinline__ void ldmx4(uint32_t* r, uint32_t addr) {
    asm volatile("ldmatrix.sync.aligned.m8n8.x4.shared.b16 {%0,%1,%2,%3}, [%4];"
        : "=r"(r[0]), "=r"(r[1]), "=r"(r[2]), "=r"(r[3]) : "r"(addr));
}
__device__ __forceinline__ void ldmx4t(uint32_t* r, uint32_t addr) {
    asm volatile("ldmatrix.sync.aligned.m8n8.x4.trans.shared.b16 {%0,%1,%2,%3}, [%4];"
        : "=r"(r[0]), "=r"(r[1]), "=r"(r[2]), "=r"(r[3]) : "r"(addr));
}
__device__ __forceinline__ void mma16816(float* c, const uint32_t* a, const uint32_t* b) {
    asm volatile("mma.sync.aligned.m16n8k16.row.col.f32.f16.f16.f32 "
        "{%0,%1,%2,%3}, {%4,%5,%6,%7}, {%8,%9}, {%0,%1,%2,%3};"
        : "+f"(c[0]), "+f"(c[1]), "+f"(c[2]), "+f"(c[3])
        : "r"(a[0]), "r"(a[1]), "r"(a[2]), "r"(a[3]), "r"(b[0]), "r"(b[1]));
}
__device__ __forceinline__ void cvt4(float4 v, uint2& uh, uint2& ul) {
    __half2 h01 = __floats2half2_rn(v.x, v.y);
    __half2 h23 = __floats2half2_rn(v.z, v.w);
    float2 f01 = __half22float2(h01);
    float2 f23 = __half22float2(h23);
    __half2 l01 = __floats2half2_rn(v.x - f01.x, v.y - f01.y);
    __half2 l23 = __floats2half2_rn(v.z - f23.x, v.w - f23.y);
    uh.x = *(uint32_t*)&h01; uh.y = *(uint32_t*)&h23;
    ul.x = *(uint32_t*)&l01; ul.y = *(uint32_t*)&l23;
}
__device__ __forceinline__ void cvt2(float v0, float v1, uint32_t& h, uint32_t& l) {
    __half2 hh = __floats2half2_rn(v0, v1);
    float2 hf = __half22float2(hh);
    __half2 ll = __floats2half2_rn(v0 - hf.x, v1 - hf.y);
    h = *(uint32_t*)&hh; l = *(uint32_t*)&ll;
}

// ---------------- small kernels ----------------
__global__ void cvt_planes(const float* __restrict__ src,
                           __half* __restrict__ dh,
                           __half* __restrict__ dl, int n4) {
    int i = blockIdx.x * 256 + threadIdx.x;
    if (i >= n4) return;
    float4 v = ((const float4*)src)[i];
    uint2 uh, ul;
    cvt4(v, uh, ul);
    ((uint2*)dh)[i] = uh;
    ((uint2*)dl)[i] = ul;
}

// hi-only conversion (weights: B operand needs no lo plane)
__global__ void cvt_hi(const float* __restrict__ src, __half* __restrict__ dh, int n4) {
    int i = blockIdx.x * 256 + threadIdx.x;
    if (i >= n4) return;
    float4 v = ((const float4*)src)[i];
    __half2 h01 = __floats2half2_rn(v.x, v.y);
    __half2 h23 = __floats2half2_rn(v.z, v.w);
    uint2 uh;
    uh.x = *(uint32_t*)&h01; uh.y = *(uint32_t*)&h23;
    ((uint2*)dh)[i] = uh;
}

__global__ void posembed_kernel(const float* __restrict__ x,
                                const int* __restrict__ tokens) {
    int i = blockIdx.x * 256 + threadIdx.x;
    int c4 = (i & 127) * 4;
    int row = i >> 7;
    int t = row >> 1, b = row & 1;
    int tok = tokens[b * T_SEQ + t];
    float4 v = ((const float4*)x)[i];
    if (tok != 0) {
        float p = (float)(t + 1);
        float* pv = (float*)&v;
#pragma unroll
        for (int e = 0; e < 4; e++) {
            int c = c4 + e;
            int ii = (c < 256) ? c : c - 256;
            float ang = p * expf((float)ii * (-9.210340371976184f / 255.0f));
            pv[e] += (c < 256) ? sinf(ang) : cosf(ang);
        }
    }
    ((float4*)g_x)[i] = v;
    uint2 uh, ul;
    cvt4(v, uh, ul);
    ((uint2*)g_xh)[i] = uh;
    ((uint2*)g_xl)[i] = ul;
}

// vsum (exact: hi+lo) + folded min/max init
__global__ void vsum_kernel(int selfmask) {
    const int bh = blockIdx.x;
    if (bh == 0 && threadIdx.x == 0) {
        if (selfmask) { g_minmax[0] = fenc(0.f); g_minmax[1] = fenc(0.f); }
        else          { g_minmax[0] = 0xFFFFFFFFu; g_minmax[1] = 0u; }
    }
    const int b = bh >> 3, h = bh & 7;
    const __half* vh = g_qkvh + b * QKV_LD + 2 * EMBED + h * HD;
    const __half* vl = g_qkvl + b * QKV_LD + 2 * EMBED + h * HD;
    const int d = threadIdx.x & 63;
    const int part = threadIdx.x >> 6;
    float s = 0.f;
    for (int i = part * 512; i < part * 512 + 512; i++) {
        size_t off = (size_t)i * ROWSTRIDE + d;
        s += __half2float(vh[off]) + __half2float(vl[off]);
    }
    __shared__ float sm[256];
    sm[threadIdx.x] = s;
    __syncthreads();
    if (threadIdx.x < 64)
        g_vsum[b * EMBED + h * HD + d] = sm[d] + sm[64 + d] + sm[128 + d] + sm[192 + d];
}

// vs2[b][n] = sum_c vsum[b][c] * Wo[n][c]
__global__ void vs2_kernel(const float* __restrict__ Wo) {
    int idx = blockIdx.x * 256 + threadIdx.x;  // 1024
    int b = idx >> 9, n = idx & 511;
    const float* vs = g_vsum + b * EMBED;
    const float* w = Wo + (size_t)n * EMBED;
    float s = 0.f;
    for (int c = 0; c < EMBED; c += 4) {
        float4 wv = *(const float4*)(w + c);
        s += vs[c] * wv.x + vs[c + 1] * wv.y + vs[c + 2] * wv.z + vs[c + 3] * wv.w;
    }
    g_vs2[idx] = s;
}

// warp-per-row LN
__global__ __launch_bounds__(256)
void ln_kernel(const float* __restrict__ res, const float* __restrict__ y,
               const float* __restrict__ gam, const float* __restrict__ bet,
               float* __restrict__ out,
               __half* __restrict__ outh, __half* __restrict__ outl) {
    const int row = blockIdx.x * 8 + (threadIdx.x >> 5);
    const int lane = threadIdx.x & 31;
    const size_t base = (size_t)row * EMBED;
    float v[16];
    float s = 0.f, q = 0.f;
#pragma unroll
    for (int k = 0; k < 4; k++) {
        const int c = lane * 4 + k * 128;
        float4 a = *(const float4*)(res + base + c);
        float4 bb = *(const float4*)(y + base + c);
        float t0 = a.x + bb.x, t1 = a.y + bb.y, t2 = a.z + bb.z, t3 = a.w + bb.w;
        v[k * 4 + 0] = t0; v[k * 4 + 1] = t1; v[k * 4 + 2] = t2; v[k * 4 + 3] = t3;
        s += t0 + t1 + t2 + t3;
        q += t0 * t0 + t1 * t1 + t2 * t2 + t3 * t3;
    }
#pragma unroll
    for (int off = 16; off > 0; off >>= 1) {
        s += __shfl_xor_sync(0xffffffffu, s, off);
        q += __shfl_xor_sync(0xffffffffu, q, off);
    }
    const float mu = s * (1.f / 512.f);
    const float var = q * (1.f / 512.f) - mu * mu;
    const float rs = rsqrtf(fmaxf(var, 0.f) + 1e-20f);
#pragma unroll
    for (int k = 0; k < 4; k++) {
        const int c = lane * 4 + k * 128;
        float4 g4 = *(const float4*)(gam + c);
        float4 b4 = *(const float4*)(bet + c);
        float4 o;
        o.x = (v[k * 4 + 0] - mu) * rs * g4.x + b4.x;
        o.y = (v[k * 4 + 1] - mu) * rs * g4.y + b4.y;
        o.z = (v[k * 4 + 2] - mu) * rs * g4.z + b4.z;
        o.w = (v[k * 4 + 3] - mu) * rs * g4.w + b4.w;
        *(float4*)(out + base + c) = o;
        uint2 uh, ul;
        cvt4(o, uh, ul);
        *(uint2*)(outh + base + c) = uh;
        *(uint2*)(outl + base + c) = ul;
    }
}

// ---------------- fused attention: O_raw = mask(QK^T*scale) @ V, + global min/max ----
// A-side (Q, S) split hi/lo; B-side (K, V) hi only.
__global__ __launch_bounds__(256, 1)
void fused_attn(int selfmask) {
    const int bid = blockIdx.x;
    const int bh = bid & 15, b = bh >> 3, h = bh & 7;
    const int tile = bid >> 4;
    const int bt = (selfmask ? (15 - tile) : tile) * 128;
    extern __shared__ char dyn[];
    const uint32_t u0 = smem_u32(dyn);
    const int tid = threadIdx.x, wid = tid >> 5, lane = tid & 31;
    const int trow = wid * 16;
    const __half* qh = g_qkvh + b * QKV_LD + h * HD;
    const __half* ql = g_qkvl + b * QKV_LD + h * HD;
    const __half* kh = g_qkvh + b * QKV_LD + EMBED + h * HD;
    const __half* vh = g_qkvh + b * QKV_LD + 2 * EMBED + h * HD;
    const int nst = selfmask ? (bt / 128 + 1) : 16;

    // prologue: Q hi/lo + stage-0 K-hi/V-hi (one group)
#pragma unroll 1
    for (int i = tid; i < 1024; i += 256) {
        int r = i >> 3, c = (i & 7) * 8;
        uint32_t dq = u0 + (r * SQ + c) * 2;
        cpa16(dq,         qh + (size_t)(bt + r) * ROWSTRIDE + c);
        cpa16(dq + 18432, ql + (size_t)(bt + r) * ROWSTRIDE + c);
        uint32_t dk = u0 + FA_QB + (r * SQ + c) * 2;
        cpa16(dk,         kh + (size_t)r * ROWSTRIDE + c);
        cpa16(dk + 18432, vh + (size_t)r * ROWSTRIDE + c);
    }
    CPA_COMMIT();

    uint32_t qfh[4][4], qfl[4][4];
    float oacc[8][4] = {};
    float lmin = 3.4e38f, lmax = -3.4e38f;

    for (int st = 0; st < nst; st++) {
        const uint32_t sb = u0 + FA_QB + (st & 1) * FA_SSTG;
        if (st + 1 < nst) {
            const uint32_t nb = u0 + FA_QB + ((st + 1) & 1) * FA_SSTG;
            const int s0 = (st + 1) * 128;
#pragma unroll 1
            for (int i = tid; i < 1024; i += 256) {
                int r = i >> 3, c = (i & 7) * 8;
                uint32_t dk = nb + (r * SQ + c) * 2;
                cpa16(dk,         kh + (size_t)(s0 + r) * ROWSTRIDE + c);
                cpa16(dk + 18432, vh + (size_t)(s0 + r) * ROWSTRIDE + c);
            }
            CPA_COMMIT();
            CPA_WAIT1();
        } else {
            CPA_WAIT0();
        }
        __syncthreads();
        if (st == 0) {
#pragma unroll
            for (int ks = 0; ks < 4; ks++) {
                uint32_t off = u0 + ((trow + (lane & 15)) * SQ + ks * 16 + (lane >> 4) * 8) * 2;
                ldmx4(qfh[ks], off);
                ldmx4(qfl[ks], off + 18432);
            }
        }
        // ---- S = Q @ K^T (K hi only) ----
        float sacc[16][4] = {};
#pragma unroll
        for (int ks = 0; ks < 4; ks++) {
#pragma unroll
            for (int j4 = 0; j4 < 8; j4++) {
                uint32_t off = sb + ((j4 * 16 + ((lane >> 4) & 1) * 8 + (lane & 7)) * SQ
                               + ks * 16 + ((lane >> 3) & 1) * 8) * 2;
                uint32_t kbh[4];
                ldmx4(kbh, off);
#pragma unroll
                for (int jj = 0; jj < 2; jj++) {
                    int j = j4 * 2 + jj;
                    mma16816(sacc[j], qfh[ks], &kbh[jj * 2]);
                    mma16816(sacc[j], qfl[ks], &kbh[jj * 2]);
                }
            }
        }
        // ---- scale/mask/minmax + register repack C-frag -> A-frag (hi/lo) ----
        const int diag = selfmask && (st == nst - 1);
        const int tg0 = bt + trow + (lane >> 2);
        const int sg0 = st * 128 + (lane & 3) * 2;
        uint32_t sfh[8][4], sfl[8][4];
#pragma unroll
        for (int j = 0; j < 16; j++) {
            float v0 = sacc[j][0] * 0.125f, v1 = sacc[j][1] * 0.125f;
            float v2 = sacc[j][2] * 0.125f, v3 = sacc[j][3] * 0.125f;
            if (diag) {
                int s = sg0 + j * 8;
                if (s + 0 > tg0) v0 = 0.f;
                if (s + 1 > tg0) v1 = 0.f;
                if (s + 0 > tg0 + 8) v2 = 0.f;
                if (s + 1 > tg0 + 8) v3 = 0.f;
            }
            lmin = fminf(lmin, fminf(fminf(v0, v1), fminf(v2, v3)));
            lmax = fmaxf(lmax, fmaxf(fmaxf(v0, v1), fmaxf(v2, v3)));
            int p = j >> 1, q = (j & 1) * 2;
            cvt2(v0, v1, sfh[p][q], sfl[p][q]);
            cvt2(v2, v3, sfh[p][q + 1], sfl[p][q + 1]);
        }
        // ---- O += S @ V (V hi only, B-frag via ldmatrix.trans) ----
        const uint32_t vb = sb + FA_VOFF;
#pragma unroll
        for (int p = 0; p < 8; p++) {
#pragma unroll
            for (int jd4 = 0; jd4 < 4; jd4++) {
                uint32_t off = vb + ((p * 16 + (lane & 15)) * SQ + jd4 * 16 + (lane >> 4) * 8) * 2;
                uint32_t vbh[4];
                ldmx4t(vbh, off);
#pragma unroll
                for (int jj = 0; jj < 2; jj++) {
                    int jd = jd4 * 2 + jj;
                    mma16816(oacc[jd], sfh[p], &vbh[jj * 2]);
                    mma16816(oacc[jd], sfl[p], &vbh[jj * 2]);
                }
            }
        }
        __syncthreads();
    }

    // ---- epilogue: write O_raw fp16 planes ----
    const int r = lane >> 2, tig = lane & 3;
#pragma unroll
    for (int jd = 0; jd < 8; jd++) {
        const int d = jd * 8 + tig * 2;
#pragma unroll
        for (int half = 0; half < 2; half++) {
            const int t = bt + trow + r + half * 8;
            uint32_t hw, lw;
            cvt2(oacc[jd][half * 2], oacc[jd][half * 2 + 1], hw, lw);
            size_t off = (size_t)(t * BATCH + b) * EMBED + h * HD + d;
            *(uint32_t*)(g_ah + off) = hw;
            *(uint32_t*)(g_al + off) = lw;
        }
    }
    // ---- global min/max ----
#pragma unroll
    for (int off = 16; off > 0; off >>= 1) {
        lmin = fminf(lmin, __shfl_xor_sync(0xffffffffu, lmin, off));
        lmax = fmaxf(lmax, __shfl_xor_sync(0xffffffffu, lmax, off));
    }
    __shared__ float rmn[8], rmx[8];
    if (lane == 0) { rmn[wid] = lmin; rmx[wid] = lmax; }
    __syncthreads();
    if (tid == 0) {
        float mn = rmn[0], mx = rmx[0];
#pragma unroll
        for (int w = 1; w < 8; w++) { mn = fminf(mn, rmn[w]); mx = fmaxf(mx, rmx[w]); }
        atomicMin(&g_minmax[0], fenc(mn));
        atomicMax(&g_minmax[1], fenc(mx));
    }
}

// ---------------- mma linear: A hi/lo planes, B hi plane only ----------------
// mode 0: fp32 out; 1: fp16 planes out; 2: planes + relu; 3: fp32 + deferred norm
#define LIN_STG 30720
__global__ __launch_bounds__(256)
void mma_linear(const __half* __restrict__ Aqh, const __half* __restrict__ Aql,
                const __half* __restrict__ Akvh, const __half* __restrict__ Akvl,
                int nsplit,
                const __half* __restrict__ Bh,
                const float* __restrict__ bias, int N, int K, int mode,
                const float* __restrict__ vs2,
                float* __restrict__ Cf, __half* __restrict__ Ch,
                __half* __restrict__ Cl) {
    extern __shared__ char dyn[];
    const uint32_t u0 = smem_u32(dyn);
    const int tid = threadIdx.x, wid = tid >> 5, lane = tid & 31;
    const int bn = blockIdx.x * 128, bm = blockIdx.y * 128;
    const __half* Ah = (bn < nsplit) ? Aqh : Akvh;
    const __half* Al = (bn < nsplit) ? Aql : Akvl;
    const int wm = (wid >> 2) * 64, wn = (wid & 3) * 32;

    float acc[4][4][4] = {};
    const int nkt = K >> 5;

#pragma unroll 1
    for (int i = tid; i < 512; i += 256) {
        int r = i >> 2, c = (i & 3) * 8;
        uint32_t d = u0 + (r * S32 + c) * 2;
        cpa16(d,         Ah + (size_t)(bm + r) * K + c);
        cpa16(d + 10240, Al + (size_t)(bm + r) * K + c);
        cpa16(d + 20480, Bh + (size_t)(bn + r) * K + c);
    }
    CPA_COMMIT();

    for (int kt = 0; kt < nkt; kt++) {
        const uint32_t sb = u0 + (kt & 1) * LIN_STG;
        if (kt + 1 < nkt) {
            const uint32_t nb = u0 + ((kt + 1) & 1) * LIN_STG;
            const int kc = (kt + 1) * 32;
#pragma unroll 1
            for (int i = tid; i < 512; i += 256) {
                int r = i >> 2, c = (i & 3) * 8;
                uint32_t d = nb + (r * S32 + c) * 2;
                cpa16(d,         Ah + (size_t)(bm + r) * K + kc + c);
                cpa16(d + 10240, Al + (size_t)(bm + r) * K + kc + c);
                cpa16(d + 20480, Bh + (size_t)(bn + r) * K + kc + c);
            }
            CPA_COMMIT();
            CPA_WAIT1();
        } else {
            CPA_WAIT0();
        }
        __syncthreads();
#pragma unroll
        for (int ks = 0; ks < 2; ks++) {
            uint32_t ah[4][4], al[4][4], bh[2][4];
#pragma unroll
            for (int i = 0; i < 4; i++) {
                uint32_t off = sb + ((wm + i * 16 + (lane & 15)) * S32 + ks * 16 + (lane >> 4) * 8) * 2;
                ldmx4(ah[i], off);
                ldmx4(al[i], off + 10240);
            }
#pragma unroll
            for (int j2 = 0; j2 < 2; j2++) {
                uint32_t off = sb + ((wn + j2 * 16 + ((lane >> 4) & 1) * 8 + (lane & 7)) * S32
                               + ks * 16 + ((lane >> 3) & 1) * 8) * 2;
                ldmx4(bh[j2], off + 20480);
            }
#pragma unroll
            for (int i = 0; i < 4; i++)
#pragma unroll
                for (int j = 0; j < 4; j++) {
                    const uint32_t* bhf = &bh[j >> 1][(j & 1) * 2];
                    mma16816(acc[i][j], ah[i], bhf);
                    mma16816(acc[i][j], al[i], bhf);
                }
        }
        __syncthreads();
    }
    float mn = 0.f, inv = 1.f;
    if (mode == 3) {
        mn = fdec(g_minmax[0]);
        inv = 1.f / (fdec(g_minmax[1]) - mn);
    }
#pragma unroll
    for (int i = 0; i < 4; i++) {
        const int m0 = bm + wm + i * 16 + (lane >> 2);
#pragma unroll
        for (int j = 0; j < 4; j++) {
            const int n0 = bn + wn + j * 8 + (lane & 3) * 2;
            float b0 = bias[n0], b1 = bias[n0 + 1];
#pragma unroll
            for (int half = 0; half < 2; half++) {
                const int m = m0 + half * 8;
                float v0 = acc[i][j][half * 2 + 0];
                float v1 = acc[i][j][half * 2 + 1];
                if (mode == 3) {
                    const int bb = m & 1;
                    v0 = (v0 - mn * vs2[bb * EMBED + n0]) * inv + b0;
                    v1 = (v1 - mn * vs2[bb * EMBED + n0 + 1]) * inv + b1;
                    float2 o = make_float2(v0, v1);
                    *(float2*)(Cf + (size_t)m * N + n0) = o;
                } else {
                    v0 += b0; v1 += b1;
                    if (mode == 2) { v0 = fmaxf(v0, 0.f); v1 = fmaxf(v1, 0.f); }
                    if (mode == 0) {
                        float2 o = make_float2(v0, v1);
                        *(float2*)(Cf + (size_t)m * N + n0) = o;
                    } else {
                        uint32_t hh, ll;
                        cvt2(v0, v1, hh, ll);
                        *(uint32_t*)(Ch + (size_t)m * N + n0) = hh;
                        *(uint32_t*)(Cl + (size_t)m * N + n0) = ll;
                    }
                }
            }
        }
    }
}

// ---------------- host orchestration ----------------
extern "C" void kernel_launch(void* const* d_in, const int* in_sizes, int n_in,
                              void* d_out, int out_size) {
    const float* x         = (const float*)d_in[0];
    const float* enc_out   = (const float*)d_in[1];
    const int*   tokens    = (const int*)d_in[2];
    const float* self_Wqkv = (const float*)d_in[3];
    const float* self_bqkv = (const float*)d_in[4];
    const float* self_Wo   = (const float*)d_in[5];
    const float* self_bo   = (const float*)d_in[6];
    const float* cross_Wqkv= (const float*)d_in[7];
    const float* cross_bqkv= (const float*)d_in[8];
    const float* cross_Wo  = (const float*)d_in[9];
    const float* cross_bo  = (const float*)d_in[10];
    const float* fc1_w     = (const float*)d_in[11];
    const float* fc1_b     = (const float*)d_in[12];
    const float* fc2_w     = (const float*)d_in[13];
    const float* fc2_b     = (const float*)d_in[14];
    const float* ln1_g     = (const float*)d_in[15];
    const float* ln1_b     = (const float*)d_in[16];
    const float* ln2_g     = (const float*)d_in[17];
    const float* ln2_b     = (const float*)d_in[18];
    const float* ln3_g     = (const float*)d_in[19];
    const float* ln3_b     = (const float*)d_in[20];

    float *px, *py, *pvs2;
    __half *pxh, *pxl, *pench, *pencl, *pqkvh, *pqkvl, *phidh, *phidl, *pah, *pal, *pwbh;
    cudaGetSymbolAddress((void**)&px, g_x);
    cudaGetSymbolAddress((void**)&py, g_y);
    cudaGetSymbolAddress((void**)&pvs2, g_vs2);
    cudaGetSymbolAddress((void**)&pxh, g_xh);
    cudaGetSymbolAddress((void**)&pxl, g_xl);
    cudaGetSymbolAddress((void**)&pench, g_ench);
    cudaGetSymbolAddress((void**)&pencl, g_encl);
    cudaGetSymbolAddress((void**)&pqkvh, g_qkvh);
    cudaGetSymbolAddress((void**)&pqkvl, g_qkvl);
    cudaGetSymbolAddress((void**)&phidh, g_hidh);
    cudaGetSymbolAddress((void**)&phidl, g_hidl);
    cudaGetSymbolAddress((void**)&pah, g_ah);
    cudaGetSymbolAddress((void**)&pal, g_al);
    cudaGetSymbolAddress((void**)&pwbh, g_wbh);

    const int SM_LIN = 2 * LIN_STG;  // 61440
    cudaFuncSetAttribute(mma_linear, cudaFuncAttributeMaxDynamicSharedMemorySize, SM_LIN);
    cudaFuncSetAttribute(fused_attn, cudaFuncAttributeMaxDynamicSharedMemorySize, FA_SMEM);

    auto cvtw = [&](const float* src, size_t off, int n) {
        cvt_hi<<<(n / 4 + 255) / 256, 256>>>(src, pwbh + off, n / 4);
    };
    cvtw(self_Wqkv, S_SQKV, 4 * QKV_LD * EMBED);
    cvtw(self_Wo,   S_SWO,  4 * EMBED * EMBED);
    cvtw(cross_Wqkv,S_CQKV, 4 * QKV_LD * EMBED);
    cvtw(cross_Wo,  S_CWO,  4 * EMBED * EMBED);
    cvtw(fc1_w,     S_FC1,  4 * FFN_DIM * EMBED);
    cvtw(fc2_w,     S_FC2,  4 * EMBED * FFN_DIM);
    cvt_planes<<<(NROWS * EMBED / 4 + 255) / 256, 256>>>(enc_out, pench, pencl, NROWS * EMBED / 4);

    posembed_kernel<<<NROWS * EMBED / 4 / 256, 256>>>(x, tokens);

    const int BIG = 1 << 30;
    for (int l = 0; l < 4; l++) {
        // ---- self attention ----
        mma_linear<<<dim3(12, 32), 256, SM_LIN>>>(pxh, pxl, pxh, pxl, BIG,
            pwbh + S_SQKV + (size_t)l * QKV_LD * EMBED,
            self_bqkv + l * QKV_LD, QKV_LD, EMBED, 1, nullptr, nullptr, pqkvh, pqkvl);
        vsum_kernel<<<16, 256>>>(1);
        fused_attn<<<256, 256, FA_SMEM>>>(1);
        vs2_kernel<<<4, 256>>>(self_Wo + (size_t)l * EMBED * EMBED);
        mma_linear<<<dim3(4, 32), 256, SM_LIN>>>(pah, pal, pah, pal, BIG,
            pwbh + S_SWO + (size_t)l * EMBED * EMBED,
            self_bo + l * EMBED, EMBED, EMBED, 3, pvs2, py, nullptr, nullptr);
        ln_kernel<<<NROWS / 8, 256>>>(px, py, ln1_g + l * EMBED, ln1_b + l * EMBED, px, pxh, pxl);

        // ---- cross attention ----
        mma_linear<<<dim3(12, 32), 256, SM_LIN>>>(pxh, pxl, pench, pencl, EMBED,
            pwbh + S_CQKV + (size_t)l * QKV_LD * EMBED,
            cross_bqkv + l * QKV_LD, QKV_LD, EMBED, 1, nullptr, nullptr, pqkvh, pqkvl);
        vsum_kernel<<<16, 256>>>(0);
        fused_attn<<<256, 256, FA_SMEM>>>(0);
        vs2_kernel<<<4, 256>>>(cross_Wo + (size_t)l * EMBED * EMBED);
        mma_linear<<<dim3(4, 32), 256, SM_LIN>>>(pah, pal, pah, pal, BIG,
            pwbh + S_CWO + (size_t)l * EMBED * EMBED,
            cross_bo + l * EMBED, EMBED, EMBED, 3, pvs2, py, nullptr, nullptr);
        ln_kernel<<<NROWS / 8, 256>>>(px, py, ln2_g + l * EMBED, ln2_b + l * EMBED, px, pxh, pxl);

        // ---- FFN ----
        mma_linear<<<dim3(16, 32), 256, SM_LIN>>>(pxh, pxl, pxh, pxl, BIG,
            pwbh + S_FC1 + (size_t)l * FFN_DIM * EMBED,
            fc1_b + l * FFN_DIM, FFN_DIM, EMBED, 2, nullptr, nullptr, phidh, phidl);
        mma_linear<<<dim3(4, 32), 256, SM_LIN>>>(phidh, phidl, phidh, phidl, BIG,
            pwbh + S_FC2 + (size_t)l * EMBED * FFN_DIM,
            fc2_b + l * EMBED, EMBED, FFN_DIM, 0, nullptr, py, nullptr, nullptr);
        float* lnout = (l == 3) ? (float*)d_out : px;
        ln_kernel<<<NROWS / 8, 256>>>(px, py, ln3_g + l * EMBED, ln3_b + l * EMBED, lnout, pxh, pxl);
    }
}